// round 14
// baseline (speedup 1.0000x reference)
#include <cuda_runtime.h>
#include <cuda_fp16.h>
#include <cstdint>
#include <cstddef>

// Problem constants
#define PB 4
#define PN 256
#define PD 256
#define PL 128
#define POUT 256

// ============================ helpers ============================
__device__ __forceinline__ uint32_t smem_to_u32(const void* smem_ptr) {
    uint32_t addr;
    asm("{ .reg .u64 tmp; cvta.to.shared.u64 tmp, %1; cvt.u32.u64 %0, tmp; }"
        : "=r"(addr) : "l"(smem_ptr));
    return addr;
}

__device__ __forceinline__ void ldsm4(uint32_t* r, uint32_t addr) {
    asm volatile("ldmatrix.sync.aligned.m8n8.x4.shared.b16 {%0,%1,%2,%3}, [%4];"
        : "=r"(r[0]), "=r"(r[1]), "=r"(r[2]), "=r"(r[3]) : "r"(addr));
}

__device__ __forceinline__ void mma_f16(float* c, const uint32_t* a, uint32_t b0, uint32_t b1) {
    asm volatile(
        "mma.sync.aligned.m16n8k16.row.col.f32.f16.f16.f32 "
        "{%0,%1,%2,%3}, {%4,%5,%6,%7}, {%8,%9}, {%0,%1,%2,%3};"
        : "+f"(c[0]), "+f"(c[1]), "+f"(c[2]), "+f"(c[3])
        : "r"(a[0]), "r"(a[1]), "r"(a[2]), "r"(a[3]), "r"(b0), "r"(b1));
}

// ---- packed f32x2 ops (sm_100+ baseline PTX) ----
typedef unsigned long long ull_t;
__device__ __forceinline__ ull_t pk2(float lo, float hi) {
    ull_t r;
    asm("mov.b64 %0, {%1, %2};" : "=l"(r)
        : "r"(__float_as_uint(lo)), "r"(__float_as_uint(hi)));
    return r;
}
__device__ __forceinline__ void upk2(ull_t v, float& lo, float& hi) {
    uint32_t a, b;
    asm("mov.b64 {%0, %1}, %2;" : "=r"(a), "=r"(b) : "l"(v));
    lo = __uint_as_float(a); hi = __uint_as_float(b);
}
__device__ __forceinline__ ull_t fma2(ull_t a, ull_t b, ull_t c) {
    ull_t d;
    asm("fma.rn.f32x2 %0, %1, %2, %3;" : "=l"(d) : "l"(a), "l"(b), "l"(c));
    return d;
}
__device__ __forceinline__ ull_t add2(ull_t a, ull_t b) {
    ull_t d;
    asm("add.rn.f32x2 %0, %1, %2;" : "=l"(d) : "l"(a), "l"(b));
    return d;
}
__device__ __forceinline__ ull_t h2_to_pk(uint32_t h2bits) {
    const __half2 h = *reinterpret_cast<const __half2*>(&h2bits);
    const float2 f = __half22float2(h);
    return pk2(f.x, f.y);
}

// ---------------- scratch (device globals; no runtime allocation) ----------------
__device__ float g_xhat [PB*PN*PL];
__device__ float g_pnorm[PB*PN*PN];
__device__ float g_adj2 [PB*PN*PN];
__device__ float g_xi0  [PB*PN*POUT];
__device__ __half g_c0  [PB*PN*POUT];   // fp16 pair-constant (layer 0)
__device__ float g_AH0  [PB*PN*POUT];
__device__ float g_xi1  [PB*PN*POUT];
__device__ __half g_c1  [PB*PN*POUT];   // fp16 pair-constant (layer 1)
__device__ float g_AH1a [PB*PN*POUT];
__device__ float g_AH1b [PB*PN*POUT];
__device__ float g_part1[512];
__device__ float g_part2[512];
// Pre-converted w_alpha image: [kh:2][n:256][k:128] fp16, 256B rows,
// XOR-swizzled by (n&7)<<4 -> ldmatrix conflict-free, verbatim staging.
// kh stride = 65536 BYTES.
__device__ __half g_wimg1[2*256*128];

// ---------------------------------------------------------------------------
// Simple row GEMM for xhat (K=128)
// ---------------------------------------------------------------------------
__global__ void rowgemm_kernel(const float* __restrict__ X, const float* __restrict__ W,
                               const float* __restrict__ bias_k, float* __restrict__ out)
{
    __shared__ float xs[4 * 256];
    const int r0 = blockIdx.x * 4;
    const int t  = threadIdx.x;
    for (int f = t; f < 4 * 256; f += 128) xs[f] = X[r0 * 256 + f];
    __syncthreads();

    float acc[4] = {0.f, 0.f, 0.f, 0.f};
#pragma unroll 8
    for (int d = 0; d < 256; ++d) {
        const float wv = __ldg(&W[d * 128 + t]);
#pragma unroll
        for (int r = 0; r < 4; ++r) acc[r] = fmaf(xs[r * 256 + d], wv, acc[r]);
    }
    const float bk = __ldg(&bias_k[t]);
#pragma unroll
    for (int r = 0; r < 4; ++r) out[(r0 + r) * 128 + t] = acc[r] + bk;
}

// ---------------------------------------------------------------------------
// Dual row GEMM (layer-0 inputs) + FUSED w_alpha image prep.
// ---------------------------------------------------------------------------
__global__ __launch_bounds__(256) void rowgemm8_dual_prep_kernel(
    const float* __restrict__ X, const float* __restrict__ W1, const float* __restrict__ W2,
    const float* __restrict__ bias_nk, const float* __restrict__ bias_k,
    const float* __restrict__ w_alpha,
    float* __restrict__ out1, __half* __restrict__ out2)
{
    extern __shared__ float dsm[];
    float* xs  = dsm;          // 2048
    float* ws1 = dsm + 2048;   // 8192
    float* ws2 = dsm + 10240;  // 8192
    const int r0 = blockIdx.x * 8;
    const int t  = threadIdx.x;

    // ---- fused prep: convert w_alpha (k=d:256, n:256) into fp16 transposed image ----
    {
        const int base = (blockIdx.x * 256 + t) * 2;
#pragma unroll
        for (int u = 0; u < 2; ++u) {
            const int e = base + u;
            const int k = e >> 8;
            const int n = e & 255;
            const __half hi = __float2half_rn(__ldg(&w_alpha[k * 256 + n]));
            const int kh = k >> 7, kk = k & 127;
            const uint32_t off = kh * 65536u + n * 256u + (uint32_t)((kk * 2) ^ ((n & 7) << 4));
            *reinterpret_cast<__half*>(reinterpret_cast<char*>(g_wimg1) + off) = hi;
        }
    }

    for (int f = t; f < 8 * 256; f += 256) xs[f] = X[r0 * 256 + f];

    float a1[8], a2[8];
#pragma unroll
    for (int r = 0; r < 8; ++r) { a1[r] = 0.f; a2[r] = 0.f; }

    for (int dt = 0; dt < 8; ++dt) {
        __syncthreads();
        const float4* W1v = reinterpret_cast<const float4*>(W1 + dt * 32 * 256);
        const float4* W2v = reinterpret_cast<const float4*>(W2 + dt * 32 * 256);
        float4* w1s = reinterpret_cast<float4*>(ws1);
        float4* w2s = reinterpret_cast<float4*>(ws2);
        for (int i = t; i < 2048; i += 256) { w1s[i] = __ldg(&W1v[i]); w2s[i] = __ldg(&W2v[i]); }
        __syncthreads();
#pragma unroll
        for (int d4 = 0; d4 < 32; d4 += 4) {
            float u0 = ws1[(d4 + 0) * 256 + t], v0 = ws2[(d4 + 0) * 256 + t];
            float u1 = ws1[(d4 + 1) * 256 + t], v1 = ws2[(d4 + 1) * 256 + t];
            float u2 = ws1[(d4 + 2) * 256 + t], v2 = ws2[(d4 + 2) * 256 + t];
            float u3 = ws1[(d4 + 3) * 256 + t], v3 = ws2[(d4 + 3) * 256 + t];
#pragma unroll
            for (int r = 0; r < 8; ++r) {
                const float4 xv = *reinterpret_cast<const float4*>(&xs[r * 256 + dt * 32 + d4]);
                a1[r] = fmaf(xv.x, u0, a1[r]); a2[r] = fmaf(xv.x, v0, a2[r]);
                a1[r] = fmaf(xv.y, u1, a1[r]); a2[r] = fmaf(xv.y, v1, a2[r]);
                a1[r] = fmaf(xv.z, u2, a1[r]); a2[r] = fmaf(xv.z, v2, a2[r]);
                a1[r] = fmaf(xv.w, u3, a1[r]); a2[r] = fmaf(xv.w, v3, a2[r]);
            }
        }
    }
    const float bk = bias_k ? __ldg(&bias_k[t]) : 0.f;
#pragma unroll
    for (int r = 0; r < 8; ++r) {
        const int row = r0 + r;
        out1[row * 256 + t] = a1[r];
        out2[row * 256 + t] = __float2half_rn(a2[r] + bk + __ldg(&bias_nk[(row & (PN - 1)) * 256 + t]));
    }
}

// ---------------------------------------------------------------------------
// Fused chain: x1 = relu(AH0 @ Wn0); xi1 = x1 @ Wvi1; c1 = fp16(x1 @ Wvj1 + bias_h1).
// ---------------------------------------------------------------------------
__global__ __launch_bounds__(256) void chain_kernel(
    const float* __restrict__ AH0, const float* __restrict__ Wn0,
    const float* __restrict__ Wvi1, const float* __restrict__ Wvj1,
    const float* __restrict__ bias_h1,
    float* __restrict__ xi1, __half* __restrict__ c1)
{
    extern __shared__ float dsm[];
    float* xs  = dsm;          // 2048
    float* ws1 = dsm + 2048;   // 8192
    float* ws2 = dsm + 10240;  // 8192
    const int r0 = blockIdx.x * 8;
    const int t  = threadIdx.x;
    for (int f = t; f < 8 * 256; f += 256) xs[f] = AH0[r0 * 256 + f];

    float acc[8];
#pragma unroll
    for (int r = 0; r < 8; ++r) acc[r] = 0.f;

    for (int dt = 0; dt < 8; ++dt) {
        __syncthreads();
        const float4* Wv = reinterpret_cast<const float4*>(Wn0 + dt * 32 * 256);
        float4* wsv = reinterpret_cast<float4*>(ws1);
        for (int i = t; i < 2048; i += 256) wsv[i] = __ldg(&Wv[i]);
        __syncthreads();
#pragma unroll
        for (int d4 = 0; d4 < 32; d4 += 4) {
            float wv0 = ws1[(d4 + 0) * 256 + t];
            float wv1 = ws1[(d4 + 1) * 256 + t];
            float wv2 = ws1[(d4 + 2) * 256 + t];
            float wv3 = ws1[(d4 + 3) * 256 + t];
#pragma unroll
            for (int r = 0; r < 8; ++r) {
                const float4 xv = *reinterpret_cast<const float4*>(&xs[r * 256 + dt * 32 + d4]);
                acc[r] = fmaf(xv.x, wv0, acc[r]);
                acc[r] = fmaf(xv.y, wv1, acc[r]);
                acc[r] = fmaf(xv.z, wv2, acc[r]);
                acc[r] = fmaf(xv.w, wv3, acc[r]);
            }
        }
    }
    __syncthreads();
#pragma unroll
    for (int r = 0; r < 8; ++r) xs[r * 256 + t] = fmaxf(acc[r], 0.f);   // x1 in smem

    float a1[8], a2[8];
#pragma unroll
    for (int r = 0; r < 8; ++r) { a1[r] = 0.f; a2[r] = 0.f; }

    for (int dt = 0; dt < 8; ++dt) {
        __syncthreads();
        const float4* W1v = reinterpret_cast<const float4*>(Wvi1 + dt * 32 * 256);
        const float4* W2v = reinterpret_cast<const float4*>(Wvj1 + dt * 32 * 256);
        float4* w1s = reinterpret_cast<float4*>(ws1);
        float4* w2s = reinterpret_cast<float4*>(ws2);
        for (int i = t; i < 2048; i += 256) { w1s[i] = __ldg(&W1v[i]); w2s[i] = __ldg(&W2v[i]); }
        __syncthreads();
#pragma unroll
        for (int d4 = 0; d4 < 32; d4 += 4) {
            float u0 = ws1[(d4 + 0) * 256 + t], v0 = ws2[(d4 + 0) * 256 + t];
            float u1 = ws1[(d4 + 1) * 256 + t], v1 = ws2[(d4 + 1) * 256 + t];
            float u2 = ws1[(d4 + 2) * 256 + t], v2 = ws2[(d4 + 2) * 256 + t];
            float u3 = ws1[(d4 + 3) * 256 + t], v3 = ws2[(d4 + 3) * 256 + t];
#pragma unroll
            for (int r = 0; r < 8; ++r) {
                const float4 xv = *reinterpret_cast<const float4*>(&xs[r * 256 + dt * 32 + d4]);
                a1[r] = fmaf(xv.x, u0, a1[r]); a2[r] = fmaf(xv.x, v0, a2[r]);
                a1[r] = fmaf(xv.y, u1, a1[r]); a2[r] = fmaf(xv.y, v1, a2[r]);
                a1[r] = fmaf(xv.z, u2, a1[r]); a2[r] = fmaf(xv.z, v2, a2[r]);
                a1[r] = fmaf(xv.w, u3, a1[r]); a2[r] = fmaf(xv.w, v3, a2[r]);
            }
        }
    }
#pragma unroll
    for (int r = 0; r < 8; ++r) {
        const int row = r0 + r;
        xi1[row * 256 + t] = a1[r];
        c1[row * 256 + t]  = __float2half_rn(a2[r] + __ldg(&bias_h1[(row & (PN - 1)) * 256 + t]));
    }
}

// ---------------------------------------------------------------------------
// Final: out = relu((A + B) @ W)
// ---------------------------------------------------------------------------
__global__ __launch_bounds__(256) void rowgemm8_sum_kernel(
    const float* __restrict__ A, const float* __restrict__ B,
    const float* __restrict__ W, float* __restrict__ out)
{
    __shared__ float xs[8 * 256];
    __shared__ float ws[32 * 256];
    const int r0 = blockIdx.x * 8;
    const int t  = threadIdx.x;
    for (int f = t; f < 8 * 256; f += 256) xs[f] = A[r0 * 256 + f] + B[r0 * 256 + f];

    float acc[8];
#pragma unroll
    for (int r = 0; r < 8; ++r) acc[r] = 0.f;

    for (int dt = 0; dt < 8; ++dt) {
        __syncthreads();
        const float4* Wv = reinterpret_cast<const float4*>(W + dt * 32 * 256);
        float4* wsv = reinterpret_cast<float4*>(ws);
        for (int i = t; i < 2048; i += 256) wsv[i] = __ldg(&Wv[i]);
        __syncthreads();
#pragma unroll
        for (int d4 = 0; d4 < 32; d4 += 4) {
            float wv0 = ws[(d4 + 0) * 256 + t];
            float wv1 = ws[(d4 + 1) * 256 + t];
            float wv2 = ws[(d4 + 2) * 256 + t];
            float wv3 = ws[(d4 + 3) * 256 + t];
#pragma unroll
            for (int r = 0; r < 8; ++r) {
                const float4 xv = *reinterpret_cast<const float4*>(&xs[r * 256 + dt * 32 + d4]);
                acc[r] = fmaf(xv.x, wv0, acc[r]);
                acc[r] = fmaf(xv.y, wv1, acc[r]);
                acc[r] = fmaf(xv.z, wv2, acc[r]);
                acc[r] = fmaf(xv.w, wv3, acc[r]);
            }
        }
    }
#pragma unroll
    for (int r = 0; r < 8; ++r) out[(r0 + r) * 256 + t] = fmaxf(acc[r], 0.f);
}

// ---------------------------------------------------------------------------
// FUSED graph-learning + AH0 kernel. One block per (b,i); 256 threads.
// Phase 1: soft_adj / adj2 / pair_norm (adj2 kept in SMEM).
// Phase 2: AH0[i,k] = sum_j adj2[i,j]*relu(H[j,k]) with H on the fly.
// rel pairs pre-packed as f32x2 in SMEM.
// ---------------------------------------------------------------------------
__global__ __launch_bounds__(256) void pair_ah0_kernel(
    const float* __restrict__ xhat,
    const float* __restrict__ adj,
    const float* __restrict__ learn_w,
    const int*   __restrict__ box_num,
    const float* __restrict__ xi0, const __half* __restrict__ c0,
    const float* __restrict__ rel, const float* __restrict__ Wt,
    float* __restrict__ soft_adj_out,
    float* __restrict__ adj2_out,
    float* __restrict__ pair_norm,
    float* __restrict__ AH0)
{
    __shared__ __align__(16) ull_t rel2_s[1536];   // packed rel pairs (12KB)
    __shared__ __align__(16) float wt_s[1536];
    __shared__ __align__(16) float adj_s[256];
    __shared__ __align__(16) float ahred[2048];
    __shared__ __align__(16) float xi_s[256];
    __shared__ float xh_s[128];
    __shared__ float w_s[128];
    __shared__ float sval[256];
    __shared__ float red[256];
    __shared__ float wsum_s, rmax_s;

    const int row = blockIdx.x;
    const int b = row >> 8;
    const int i = row & 255;
    const int t = threadIdx.x;
    const int wid = t >> 5;
    const int lane = t & 31;

    // ---- stage phase-2 data early (overlaps with phase-1 compute) ----
    const float* relrow = rel + (size_t)row * 256 * 6;
    for (int f = t; f < 1536; f += 256) {
        const float rv = relrow[f];
        rel2_s[f] = pk2(rv, rv);
        wt_s[f] = Wt[f];
    }
    xi_s[t] = xi0[row * 256 + t];

    if (t < 128) { xh_s[t] = xhat[row * 128 + t]; w_s[t] = learn_w[t]; }
    __syncthreads();
    if (t == 0) {
        float s = 0.f;
        for (int d = 0; d < 128; ++d) s += w_s[d];
        wsum_s = s;
    }
    __syncthreads();

    // ===== phase 1: pair / soft_adj =====
    const int bn = box_num[b];
    const bool vi = (i < bn);
    const float wsum = wsum_s;
    const float4 xi4 = reinterpret_cast<const float4*>(xh_s)[lane];
    const float4 w4  = reinterpret_cast<const float4*>(w_s)[lane];

    for (int j = wid; j < 256; j += 8) {
        const float4 xj4 = __ldg(reinterpret_cast<const float4*>(xhat + (b * 256 + j) * 128) + lane);
        const float d0 = xi4.x - xj4.x, d1 = xi4.y - xj4.y;
        const float d2 = xi4.z - xj4.z, d3 = xi4.w - xj4.w;
        float s = fabsf(d0) * w4.x + fabsf(d1) * w4.y + fabsf(d2) * w4.z + fabsf(d3) * w4.w;
        float q = d0 * d0 + d1 * d1 + d2 * d2 + d3 * d3;
#pragma unroll
        for (int off = 16; off; off >>= 1) {
            s += __shfl_down_sync(0xffffffffu, s, off);
            q += __shfl_down_sync(0xffffffffu, q, off);
        }
        if (lane == 0) {
            const float m = (vi && (j < bn)) ? 0.f : -1.f;
            float v = s + m * wsum;
            v = (v > 0.f) ? v : 0.01f * v;
            sval[j] = v;
            pair_norm[row * 256 + j] = sqrtf(q + 1e-12f);
        }
    }
    __syncthreads();

    const float v = sval[t];
    red[t] = v;
    __syncthreads();
    for (int sft = 128; sft; sft >>= 1) {
        if (t < sft) red[t] = fmaxf(red[t], red[t + sft]);
        __syncthreads();
    }
    if (t == 0) rmax_s = red[0];
    __syncthreads();

    const float a = adj[row * 256 + t];
    const float e = expf(v - rmax_s) * a;
    red[t] = e;
    __syncthreads();
    for (int sft = 128; sft; sft >>= 1) {
        if (t < sft) red[t] += red[t + sft];
        __syncthreads();
    }
    const float sa = e / red[0] + 1e-10f;
    soft_adj_out[row * 256 + t] = sa;
    const float a2v = a * sa;
    adj2_out[row * 256 + t] = a2v;
    adj_s[t] = a2v;
    __syncthreads();

    // ===== phase 2: AH0 =====
    const uint2* c0q = reinterpret_cast<const uint2*>(c0 + b * 65536);

#pragma unroll
    for (int kq2 = 0; kq2 < 2; ++kq2) {
        const int q = lane + 32 * kq2;
        const ulonglong2 xiv = *reinterpret_cast<const ulonglong2*>(&xi_s[4 * q]);
        ull_t wt2[6][2];
#pragma unroll
        for (int c = 0; c < 6; ++c) {
            const ulonglong2 w = *reinterpret_cast<const ulonglong2*>(&wt_s[c * 256 + 4 * q]);
            wt2[c][0] = w.x; wt2[c][1] = w.y;
        }

        float ah0 = 0.f, ah1 = 0.f, ah2 = 0.f, ah3 = 0.f;
#pragma unroll 1
        for (int s = 0; s < 32; s += 8) {
            uint2 cv[8];
#pragma unroll
            for (int u = 0; u < 8; ++u)
                cv[u] = __ldg(&c0q[(wid * 32 + s + u) * 64 + q]);
#pragma unroll
            for (int u = 0; u < 8; ++u) {
                const int j = wid * 32 + s + u;
                const ull_t* rj = rel2_s + j * 6;
                ull_t t0 = add2(xiv.x, h2_to_pk(cv[u].x));
                ull_t t1 = add2(xiv.y, h2_to_pk(cv[u].y));
#pragma unroll
                for (int c = 0; c < 6; ++c) {
                    const ull_t rp = rj[c];
                    t0 = fma2(rp, wt2[c][0], t0);
                    t1 = fma2(rp, wt2[c][1], t1);
                }
                float h0, h1, h2, h3;
                upk2(t0, h0, h1);
                upk2(t1, h2, h3);
                const float aw = adj_s[j];
                ah0 = fmaf(aw, fmaxf(h0, 0.f), ah0);
                ah1 = fmaf(aw, fmaxf(h1, 0.f), ah1);
                ah2 = fmaf(aw, fmaxf(h2, 0.f), ah2);
                ah3 = fmaf(aw, fmaxf(h3, 0.f), ah3);
            }
        }
        float4 o; o.x = ah0; o.y = ah1; o.z = ah2; o.w = ah3;
        *reinterpret_cast<float4*>(&ahred[wid * 256 + 4 * q]) = o;
    }
    __syncthreads();

    float s = 0.f;
#pragma unroll
    for (int g = 0; g < 8; ++g) s += ahred[g * 256 + t];
    AH0[row * 256 + t] = s;
}

// ---------------------------------------------------------------------------
// gl_loss two-phase reduction.
// ---------------------------------------------------------------------------
__global__ void glloss_part_kernel(const float* __restrict__ soft_adj,
                                   const float* __restrict__ pair_norm)
{
    const int blk = blockIdx.x;
    const int b = blk >> 7;
    const int t = threadIdx.x;
    const int base = b * 65536 + (blk & 127) * 512;
    float s1 = 0.f, s2 = 0.f;
#pragma unroll
    for (int u = 0; u < 2; ++u) {
        const int idx = base + u * 256 + t;
        const float s = soft_adj[idx];
        s1 += expf(s + pair_norm[idx]);
        s2 += s * s;
    }
    __shared__ float r1[256], r2[256];
    r1[t] = s1; r2[t] = s2;
    __syncthreads();
    for (int sft = 128; sft; sft >>= 1) {
        if (t < sft) { r1[t] += r1[t + sft]; r2[t] += r2[t + sft]; }
        __syncthreads();
    }
    if (t == 0) { g_part1[blk] = r1[0]; g_part2[blk] = r2[0]; }
}

__global__ void glloss_fin_kernel(const int* __restrict__ box_num, float* __restrict__ gl_out)
{
    const int b = blockIdx.x;
    const int t = threadIdx.x;
    __shared__ float r1[128], r2[128];
    r1[t] = g_part1[b * 128 + t];
    r2[t] = g_part2[b * 128 + t];
    __syncthreads();
    for (int sft = 64; sft; sft >>= 1) {
        if (t < sft) { r1[t] += r1[t + sft]; r2[t] += r2[t + sft]; }
        __syncthreads();
    }
    if (t == 0) {
        const float bnf = (float)box_num[b];
        gl_out[b] = r1[0] / (bnf * bnf) + 1e-4f * sqrtf(r2[0]);
    }
}

// ---------------------------------------------------------------------------
// Kernel C: fused layer0 GEMM + layer1 reduction, one jh half PER BLOCK.
// Grid (1024, 2). rel pairs pre-packed in SMEM; c0/c1 fp16.
// ---------------------------------------------------------------------------
// SMEM byte offsets
#define SM_A       0         // 128 j x 256 k fp16, 512B rows, xor-swizzled = 65536
#define SM_B1      65536     // 32768
#define SM_REL2    98304     // 6144 (128 j x 6 packed f32x2)
#define SM_ADJ     104448    // 1024
#define SM_AHRED   105472    // 8192 (8 warps x 256 n)
#define SM_XI      113664    // 1024
#define SM_XI1     114688    // 1024
#define SM_TOTAL   115712

__global__ void __launch_bounds__(256, 2) layer01_mma_kernel(
    const float* __restrict__ xi0, const __half* __restrict__ c0,
    const float* __restrict__ rel, const float* __restrict__ Wt,
    const float* __restrict__ adj2,
    const float* __restrict__ xi1, const __half* __restrict__ c1,
    float* __restrict__ AH1a, float* __restrict__ AH1b)
{
    extern __shared__ char sm[];
    const uint32_t sb = smem_to_u32(sm);
    ull_t* rel2_s = reinterpret_cast<ull_t*>(sm + SM_REL2);
    float* adj_s  = reinterpret_cast<float*>(sm + SM_ADJ);
    float* ah1red = reinterpret_cast<float*>(sm + SM_AHRED);
    float* xi_s   = reinterpret_cast<float*>(sm + SM_XI);
    float* xi1_s  = reinterpret_cast<float*>(sm + SM_XI1);

    const int t = threadIdx.x;
    const int wid = t >> 5;
    const int lane = t & 31;
    const int row = blockIdx.x;      // b*256 + i
    const int jh  = blockIdx.y;      // 0 or 1
    const int b = row >> 8;

    adj_s[t]  = adj2[row * 256 + t];
    xi_s[t]   = xi0[row * 256 + t];
    xi1_s[t]  = xi1[row * 256 + t];
    const float* relrow = rel + ((size_t)row * 256 + jh * 128) * 6;
    for (int f = t; f < 768; f += 256) {
        const float rv = relrow[f];
        rel2_s[f] = pk2(rv, rv);
    }
    __syncthreads();

    const uint2* c0q = reinterpret_cast<const uint2*>(c0 + b * 65536);
    const __half* c1b = c1 + b * 65536;

    // --- per-lane ldmatrix address components ---
    const int jrl = wid * 16 + (lane & 15);
    const uint32_t acolByte = (uint32_t)((lane >> 4) * 16);
    const uint32_t jmask = (uint32_t)((jrl & 7) << 4);
    const uint32_t aRowByte = (uint32_t)jrl * 512u;
    const int nrow_l = (lane & 7) | ((lane & 16) >> 1);
    const uint32_t kbB = (uint32_t)(((lane >> 3) & 1) * 16);
    const uint32_t nmask = (uint32_t)((nrow_l & 7) << 4);
    const uint32_t bRowByte = (uint32_t)nrow_l * 256u;

    const int r  = lane >> 2;    // 0..7
    const int cq = lane & 3;     // 0..3

    // ---- build H half (128 j x 256 k) as fp16; 4 k per iter, MLP=4 ----
#pragma unroll
    for (int kq2 = 0; kq2 < 2; ++kq2) {
        const int q = lane + 32 * kq2;     // k-quad 0..63
        const ulonglong2 xiv = *reinterpret_cast<const ulonglong2*>(&xi_s[4 * q]);
        ull_t wt2[6][2];
#pragma unroll
        for (int c = 0; c < 6; ++c) {
            const float2 wa = __ldg(reinterpret_cast<const float2*>(&Wt[c * 256 + 4 * q]));
            const float2 wb = __ldg(reinterpret_cast<const float2*>(&Wt[c * 256 + 4 * q + 2]));
            wt2[c][0] = pk2(wa.x, wa.y);
            wt2[c][1] = pk2(wb.x, wb.y);
        }

#pragma unroll 1
        for (int s = 0; s < 16; s += 4) {
            uint2 cv[4];
#pragma unroll
            for (int u = 0; u < 4; ++u) {
                const int j = jh * 128 + wid * 16 + s + u;
                cv[u] = __ldg(&c0q[j * 64 + q]);
            }
#pragma unroll
            for (int u = 0; u < 4; ++u) {
                const int jl = wid * 16 + s + u;
                const ull_t* rj = rel2_s + jl * 6;
                ull_t t0 = add2(xiv.x, h2_to_pk(cv[u].x));
                ull_t t1 = add2(xiv.y, h2_to_pk(cv[u].y));
#pragma unroll
                for (int c = 0; c < 6; ++c) {
                    const ull_t rp = rj[c];
                    t0 = fma2(rp, wt2[c][0], t0);
                    t1 = fma2(rp, wt2[c][1], t1);
                }
                float h0, h1, h2, h3;
                upk2(t0, h0, h1);
                upk2(t1, h2, h3);
                __half2 ha = __floats2half2_rn(fmaxf(h0, 0.f), fmaxf(h1, 0.f));
                __half2 hb = __floats2half2_rn(fmaxf(h2, 0.f), fmaxf(h3, 0.f));
                uint2 hv;
                hv.x = *reinterpret_cast<uint32_t*>(&ha);
                hv.y = *reinterpret_cast<uint32_t*>(&hb);
                const uint32_t off = (uint32_t)jl * 512u + ((uint32_t)(8 * q) ^ ((uint32_t)(jl & 7) << 4));
                *reinterpret_cast<uint2*>(sm + SM_A + off) = hv;
            }
        }
    }

#pragma unroll 1
    for (int nc = 0; nc < 2; ++nc) {
        float C[16][4];
#pragma unroll
        for (int nt = 0; nt < 16; ++nt)
#pragma unroll
            for (int u = 0; u < 4; ++u) C[nt][u] = 0.f;

#pragma unroll 1
        for (int kh = 0; kh < 2; ++kh) {
            __syncthreads();   // prior B consumers done (first iter: A build visibility)
            {
                const uint4* s1 = reinterpret_cast<const uint4*>(
                    reinterpret_cast<const char*>(g_wimg1) + kh * 65536 + nc * 32768);
                uint4* d1 = reinterpret_cast<uint4*>(sm + SM_B1);
                for (int i = t; i < 2048; i += 256) d1[i] = __ldg(&s1[i]);
            }
            __syncthreads();

            // ---- HMMA: C += A * B ----
#pragma unroll 1
            for (int ks = 0; ks < 8; ++ks) {
                const uint32_t aoff = ((uint32_t)((kh * 8 + ks) * 32) + acolByte) ^ jmask;
                const uint32_t boff = ((uint32_t)(ks * 32) + kbB) ^ nmask;
                uint32_t Ah[4];
                ldsm4(Ah, sb + SM_A + aRowByte + aoff);

                uint32_t bb[4];
#pragma unroll
                for (int p = 0; p < 8; ++p) {
                    ldsm4(bb, sb + SM_B1 + (uint32_t)p * 4096 + bRowByte + boff);
                    mma_f16(C[2 * p],     Ah, bb[0], bb[1]);
                    mma_f16(C[2 * p + 1], Ah, bb[2], bb[3]);
                }
            }
        }

        // ---- fused layer1 epilogue: consume alpha1 = relu(C) in registers ----
        {
            float acc0[16], acc1[16];
#pragma unroll
            for (int nt = 0; nt < 16; ++nt) { acc0[nt] = 0.f; acc1[nt] = 0.f; }

            const int j1 = jh * 128 + wid * 16 + r;
            const int j2 = j1 + 8;
            const float aw1 = adj_s[j1];
            const float aw2 = adj_s[j2];

#pragma unroll
            for (int ntb = 0; ntb < 16; ntb += 4) {
                uint32_t cA[4], cB[4];
#pragma unroll
                for (int u = 0; u < 4; ++u) {
                    const int n0 = nc * 128 + (ntb + u) * 8 + 2 * cq;
                    cA[u] = __ldg(reinterpret_cast<const uint32_t*>(c1b + j1 * 256 + n0));
                    cB[u] = __ldg(reinterpret_cast<const uint32_t*>(c1b + j2 * 256 + n0));
                }
#pragma unroll
                for (int u = 0; u < 4; ++u) {
                    const int nt = ntb + u;
                    const int n0 = nc * 128 + nt * 8 + 2 * cq;
                    const float2 fA = __half22float2(*reinterpret_cast<const __half2*>(&cA[u]));
                    const float2 fB = __half22float2(*reinterpret_cast<const __half2*>(&cB[u]));
                    const float x0 = xi1_s[n0];
                    const float x1v = xi1_s[n0 + 1];
                    const float a0 = fmaxf(C[nt][0], 0.f);
                    const float a1 = fmaxf(C[nt][1], 0.f);
                    const float a2 = fmaxf(C[nt][2], 0.f);
                    const float a3 = fmaxf(C[nt][3], 0.f);
                    acc0[nt] = fmaf(aw1, fmaxf(x0 + fA.x + a0, 0.f), acc0[nt]);
                    acc1[nt] = fmaf(aw1, fmaxf(x1v + fA.y + a1, 0.f), acc1[nt]);
                    acc0[nt] = fmaf(aw2, fmaxf(x0 + fB.x + a2, 0.f), acc0[nt]);
                    acc1[nt] = fmaf(aw2, fmaxf(x1v + fB.y + a3, 0.f), acc1[nt]);
                }
            }

#pragma unroll
            for (int nt = 0; nt < 16; ++nt) {
                float v0 = acc0[nt], v1 = acc1[nt];
#pragma unroll
                for (int off = 4; off <= 16; off <<= 1) {
                    v0 += __shfl_xor_sync(0xffffffffu, v0, off);
                    v1 += __shfl_xor_sync(0xffffffffu, v1, off);
                }
                if (r == 0) {
                    const int n0 = nc * 128 + nt * 8 + 2 * cq;
                    ah1red[wid * 256 + n0]     = v0;
                    ah1red[wid * 256 + n0 + 1] = v1;
                }
            }
        }
    }
    __syncthreads();

    // cross-warp reduce -> AH1part[jh]
    {
        float s = 0.f;
#pragma unroll
        for (int g = 0; g < 8; ++g) s += ah1red[g * 256 + t];
        float* dst = jh ? AH1b : AH1a;
        dst[row * 256 + t] = s;
    }
}

// ---------------------------------------------------------------------------
extern "C" void kernel_launch(void* const* d_in, const int* in_sizes, int n_in,
                              void* d_out, int out_size)
{
    (void)in_sizes; (void)n_in; (void)out_size;

    const float* x        = (const float*)d_in[0];
    const float* rel      = (const float*)d_in[1];
    const float* adj      = (const float*)d_in[2];
    const int*   bnum     = (const int*)  d_in[3];
    const float* Wt       = (const float*)d_in[4];
    const float* b_alpha  = (const float*)d_in[5];
    const float* W_proj   = (const float*)d_in[6];
    const float* b_proj   = (const float*)d_in[7];
    const float* learn_w  = (const float*)d_in[8];
    const float* w_alpha0 = (const float*)d_in[9];
    const float* w_vi0    = (const float*)d_in[10];
    const float* w_vj0    = (const float*)d_in[11];
    const float* bias_h0  = (const float*)d_in[12];
    const float* w_node0  = (const float*)d_in[13];
    /* d_in[14] = l1_w_alpha: unused (alpha2 discarded) */
    const float* w_vi1    = (const float*)d_in[15];
    const float* w_vj1    = (const float*)d_in[16];
    const float* bias_h1  = (const float*)d_in[17];
    const float* w_node1  = (const float*)d_in[18];

    float* out      = (float*)d_out;
    float* out_x2   = out;
    float* out_sadj = out + 262144;
    float* out_gl   = out + 524288;

    float *xhat, *pnorm, *adj2, *xi0, *AH0, *xi1, *AH1a, *AH1b;
    __half *c0, *c1;
    cudaGetSymbolAddress((void**)&xhat,  g_xhat);
    cudaGetSymbolAddress((void**)&pnorm, g_pnorm);
    cudaGetSymbolAddress((void**)&adj2,  g_adj2);
    cudaGetSymbolAddress((void**)&xi0,   g_xi0);
    cudaGetSymbolAddress((void**)&c0,    g_c0);
    cudaGetSymbolAddress((void**)&AH0,   g_AH0);
    cudaGetSymbolAddress((void**)&xi1,   g_xi1);
    cudaGetSymbolAddress((void**)&c1,    g_c1);
    cudaGetSymbolAddress((void**)&AH1a,  g_AH1a);
    cudaGetSymbolAddress((void**)&AH1b,  g_AH1b);

    const int DUAL_SMEM = 18432 * 4;

    cudaFuncSetAttribute(rowgemm8_dual_prep_kernel, cudaFuncAttributeMaxDynamicSharedMemorySize, DUAL_SMEM);
    rowgemm8_dual_prep_kernel<<<128, 256, DUAL_SMEM>>>(x, w_vi0, w_vj0, bias_h0, b_alpha, w_alpha0, xi0, c0);

    rowgemm_kernel<<<256, 128>>>(x, W_proj, b_proj, xhat);

    // fused pair + AH0 (adj2 via SMEM)
    pair_ah0_kernel<<<1024, 256>>>(xhat, adj, learn_w, bnum, xi0, c0, rel, Wt,
                                   out_sadj, adj2, pnorm, AH0);

    cudaFuncSetAttribute(chain_kernel, cudaFuncAttributeMaxDynamicSharedMemorySize, DUAL_SMEM);
    chain_kernel<<<128, 256, DUAL_SMEM>>>(AH0, w_node0, w_vi1, w_vj1, bias_h1, xi1, c1);

    cudaFuncSetAttribute(layer01_mma_kernel, cudaFuncAttributeMaxDynamicSharedMemorySize, SM_TOTAL);
    layer01_mma_kernel<<<dim3(1024, 2), 256, SM_TOTAL>>>(xi0, c0, rel, Wt, adj2, xi1, c1, AH1a, AH1b);

    glloss_part_kernel<<<512, 256>>>(out_sadj, pnorm);
    glloss_fin_kernel<<<4, 128>>>(bnum, out_gl);
    rowgemm8_sum_kernel<<<128, 256>>>(AH1a, AH1b, w_node1, out_x2);
}

// round 15
// speedup vs baseline: 1.0260x; 1.0260x over previous
#include <cuda_runtime.h>
#include <cuda_fp16.h>
#include <cstdint>
#include <cstddef>

// Problem constants
#define PB 4
#define PN 256
#define PD 256
#define PL 128
#define POUT 256

// ============================ helpers ============================
__device__ __forceinline__ uint32_t smem_to_u32(const void* smem_ptr) {
    uint32_t addr;
    asm("{ .reg .u64 tmp; cvta.to.shared.u64 tmp, %1; cvt.u32.u64 %0, tmp; }"
        : "=r"(addr) : "l"(smem_ptr));
    return addr;
}

__device__ __forceinline__ void ldsm4(uint32_t* r, uint32_t addr) {
    asm volatile("ldmatrix.sync.aligned.m8n8.x4.shared.b16 {%0,%1,%2,%3}, [%4];"
        : "=r"(r[0]), "=r"(r[1]), "=r"(r[2]), "=r"(r[3]) : "r"(addr));
}

__device__ __forceinline__ void mma_f16(float* c, const uint32_t* a, uint32_t b0, uint32_t b1) {
    asm volatile(
        "mma.sync.aligned.m16n8k16.row.col.f32.f16.f16.f32 "
        "{%0,%1,%2,%3}, {%4,%5,%6,%7}, {%8,%9}, {%0,%1,%2,%3};"
        : "+f"(c[0]), "+f"(c[1]), "+f"(c[2]), "+f"(c[3])
        : "r"(a[0]), "r"(a[1]), "r"(a[2]), "r"(a[3]), "r"(b0), "r"(b1));
}

// ---- packed f32x2 ops (sm_100+ baseline PTX) ----
typedef unsigned long long ull_t;
__device__ __forceinline__ ull_t pk2(float lo, float hi) {
    ull_t r;
    asm("mov.b64 %0, {%1, %2};" : "=l"(r)
        : "r"(__float_as_uint(lo)), "r"(__float_as_uint(hi)));
    return r;
}
__device__ __forceinline__ void upk2(ull_t v, float& lo, float& hi) {
    uint32_t a, b;
    asm("mov.b64 {%0, %1}, %2;" : "=r"(a), "=r"(b) : "l"(v));
    lo = __uint_as_float(a); hi = __uint_as_float(b);
}
__device__ __forceinline__ ull_t fma2(ull_t a, ull_t b, ull_t c) {
    ull_t d;
    asm("fma.rn.f32x2 %0, %1, %2, %3;" : "=l"(d) : "l"(a), "l"(b), "l"(c));
    return d;
}
__device__ __forceinline__ ull_t add2(ull_t a, ull_t b) {
    ull_t d;
    asm("add.rn.f32x2 %0, %1, %2;" : "=l"(d) : "l"(a), "l"(b));
    return d;
}
__device__ __forceinline__ ull_t h2_to_pk(uint32_t h2bits) {
    const __half2 h = *reinterpret_cast<const __half2*>(&h2bits);
    const float2 f = __half22float2(h);
    return pk2(f.x, f.y);
}

// ---------------- scratch (device globals; no runtime allocation) ----------------
__device__ float g_xhat [PB*PN*PL];
__device__ float g_pnorm[PB*PN*PN];
__device__ float g_adj2 [PB*PN*PN];
__device__ float g_xi0  [PB*PN*POUT];
__device__ __half g_c0  [PB*PN*POUT];   // fp16 pair-constant (layer 0)
__device__ float g_AH0  [PB*PN*POUT];
__device__ float g_xi1  [PB*PN*POUT];
__device__ __half g_c1  [PB*PN*POUT];   // fp16 pair-constant (layer 1)
__device__ float g_AH1a [PB*PN*POUT];
__device__ float g_AH1b [PB*PN*POUT];
__device__ float g_part1[512];
__device__ float g_part2[512];
// Pre-converted w_alpha image: [kh:2][n:256][k:128] fp16, 256B rows,
// XOR-swizzled by (n&7)<<4 -> ldmatrix conflict-free, verbatim staging.
// kh stride = 65536 BYTES.
__device__ __half g_wimg1[2*256*128];

// ---------------------------------------------------------------------------
// Simple row GEMM for xhat (K=128)
// ---------------------------------------------------------------------------
__global__ void rowgemm_kernel(const float* __restrict__ X, const float* __restrict__ W,
                               const float* __restrict__ bias_k, float* __restrict__ out)
{
    __shared__ float xs[4 * 256];
    const int r0 = blockIdx.x * 4;
    const int t  = threadIdx.x;
    for (int f = t; f < 4 * 256; f += 128) xs[f] = X[r0 * 256 + f];
    __syncthreads();

    float acc[4] = {0.f, 0.f, 0.f, 0.f};
#pragma unroll 8
    for (int d = 0; d < 256; ++d) {
        const float wv = __ldg(&W[d * 128 + t]);
#pragma unroll
        for (int r = 0; r < 4; ++r) acc[r] = fmaf(xs[r * 256 + d], wv, acc[r]);
    }
    const float bk = __ldg(&bias_k[t]);
#pragma unroll
    for (int r = 0; r < 4; ++r) out[(r0 + r) * 128 + t] = acc[r] + bk;
}

// ---------------------------------------------------------------------------
// Dual row GEMM (layer-0 inputs) + FUSED w_alpha image prep.
// 4 rows/block, grid = 256 (full-chip occupancy for latency hiding).
// ---------------------------------------------------------------------------
__global__ __launch_bounds__(256) void rowgemm4_dual_prep_kernel(
    const float* __restrict__ X, const float* __restrict__ W1, const float* __restrict__ W2,
    const float* __restrict__ bias_nk, const float* __restrict__ bias_k,
    const float* __restrict__ w_alpha,
    float* __restrict__ out1, __half* __restrict__ out2)
{
    extern __shared__ float dsm[];
    float* xs  = dsm;          // 1024
    float* ws1 = dsm + 1024;   // 8192
    float* ws2 = dsm + 9216;   // 8192
    const int r0 = blockIdx.x * 4;
    const int t  = threadIdx.x;

    // ---- fused prep: convert w_alpha (k=d:256, n:256) into fp16 transposed image ----
    {
        const int e = blockIdx.x * 256 + t;   // one element per thread, 256 blocks
        const int k = e >> 8;
        const int n = e & 255;
        const __half hi = __float2half_rn(__ldg(&w_alpha[k * 256 + n]));
        const int kh = k >> 7, kk = k & 127;
        const uint32_t off = kh * 65536u + n * 256u + (uint32_t)((kk * 2) ^ ((n & 7) << 4));
        *reinterpret_cast<__half*>(reinterpret_cast<char*>(g_wimg1) + off) = hi;
    }

    for (int f = t; f < 4 * 256; f += 256) xs[f] = X[r0 * 256 + f];

    float a1[4], a2[4];
#pragma unroll
    for (int r = 0; r < 4; ++r) { a1[r] = 0.f; a2[r] = 0.f; }

    for (int dt = 0; dt < 8; ++dt) {
        __syncthreads();
        const float4* W1v = reinterpret_cast<const float4*>(W1 + dt * 32 * 256);
        const float4* W2v = reinterpret_cast<const float4*>(W2 + dt * 32 * 256);
        float4* w1s = reinterpret_cast<float4*>(ws1);
        float4* w2s = reinterpret_cast<float4*>(ws2);
        for (int i = t; i < 2048; i += 256) { w1s[i] = __ldg(&W1v[i]); w2s[i] = __ldg(&W2v[i]); }
        __syncthreads();
#pragma unroll
        for (int d4 = 0; d4 < 32; d4 += 4) {
            float u0 = ws1[(d4 + 0) * 256 + t], v0 = ws2[(d4 + 0) * 256 + t];
            float u1 = ws1[(d4 + 1) * 256 + t], v1 = ws2[(d4 + 1) * 256 + t];
            float u2 = ws1[(d4 + 2) * 256 + t], v2 = ws2[(d4 + 2) * 256 + t];
            float u3 = ws1[(d4 + 3) * 256 + t], v3 = ws2[(d4 + 3) * 256 + t];
#pragma unroll
            for (int r = 0; r < 4; ++r) {
                const float4 xv = *reinterpret_cast<const float4*>(&xs[r * 256 + dt * 32 + d4]);
                a1[r] = fmaf(xv.x, u0, a1[r]); a2[r] = fmaf(xv.x, v0, a2[r]);
                a1[r] = fmaf(xv.y, u1, a1[r]); a2[r] = fmaf(xv.y, v1, a2[r]);
                a1[r] = fmaf(xv.z, u2, a1[r]); a2[r] = fmaf(xv.z, v2, a2[r]);
                a1[r] = fmaf(xv.w, u3, a1[r]); a2[r] = fmaf(xv.w, v3, a2[r]);
            }
        }
    }
    const float bk = bias_k ? __ldg(&bias_k[t]) : 0.f;
#pragma unroll
    for (int r = 0; r < 4; ++r) {
        const int row = r0 + r;
        out1[row * 256 + t] = a1[r];
        out2[row * 256 + t] = __float2half_rn(a2[r] + bk + __ldg(&bias_nk[(row & (PN - 1)) * 256 + t]));
    }
}

// ---------------------------------------------------------------------------
// Fused chain: x1 = relu(AH0 @ Wn0); xi1 = x1 @ Wvi1; c1 = fp16(x1 @ Wvj1 + bias_h1).
// 4 rows/block, grid = 256.
// ---------------------------------------------------------------------------
__global__ __launch_bounds__(256) void chain_kernel(
    const float* __restrict__ AH0, const float* __restrict__ Wn0,
    const float* __restrict__ Wvi1, const float* __restrict__ Wvj1,
    const float* __restrict__ bias_h1,
    float* __restrict__ xi1, __half* __restrict__ c1)
{
    extern __shared__ float dsm[];
    float* xs  = dsm;          // 1024
    float* ws1 = dsm + 1024;   // 8192
    float* ws2 = dsm + 9216;   // 8192
    const int r0 = blockIdx.x * 4;
    const int t  = threadIdx.x;
    for (int f = t; f < 4 * 256; f += 256) xs[f] = AH0[r0 * 256 + f];

    float acc[4] = {0.f, 0.f, 0.f, 0.f};

    for (int dt = 0; dt < 8; ++dt) {
        __syncthreads();
        const float4* Wv = reinterpret_cast<const float4*>(Wn0 + dt * 32 * 256);
        float4* wsv = reinterpret_cast<float4*>(ws1);
        for (int i = t; i < 2048; i += 256) wsv[i] = __ldg(&Wv[i]);
        __syncthreads();
#pragma unroll
        for (int d4 = 0; d4 < 32; d4 += 4) {
            float wv0 = ws1[(d4 + 0) * 256 + t];
            float wv1 = ws1[(d4 + 1) * 256 + t];
            float wv2 = ws1[(d4 + 2) * 256 + t];
            float wv3 = ws1[(d4 + 3) * 256 + t];
#pragma unroll
            for (int r = 0; r < 4; ++r) {
                const float4 xv = *reinterpret_cast<const float4*>(&xs[r * 256 + dt * 32 + d4]);
                acc[r] = fmaf(xv.x, wv0, acc[r]);
                acc[r] = fmaf(xv.y, wv1, acc[r]);
                acc[r] = fmaf(xv.z, wv2, acc[r]);
                acc[r] = fmaf(xv.w, wv3, acc[r]);
            }
        }
    }
    __syncthreads();
#pragma unroll
    for (int r = 0; r < 4; ++r) xs[r * 256 + t] = fmaxf(acc[r], 0.f);   // x1 in smem

    float a1[4], a2[4];
#pragma unroll
    for (int r = 0; r < 4; ++r) { a1[r] = 0.f; a2[r] = 0.f; }

    for (int dt = 0; dt < 8; ++dt) {
        __syncthreads();
        const float4* W1v = reinterpret_cast<const float4*>(Wvi1 + dt * 32 * 256);
        const float4* W2v = reinterpret_cast<const float4*>(Wvj1 + dt * 32 * 256);
        float4* w1s = reinterpret_cast<float4*>(ws1);
        float4* w2s = reinterpret_cast<float4*>(ws2);
        for (int i = t; i < 2048; i += 256) { w1s[i] = __ldg(&W1v[i]); w2s[i] = __ldg(&W2v[i]); }
        __syncthreads();
#pragma unroll
        for (int d4 = 0; d4 < 32; d4 += 4) {
            float u0 = ws1[(d4 + 0) * 256 + t], v0 = ws2[(d4 + 0) * 256 + t];
            float u1 = ws1[(d4 + 1) * 256 + t], v1 = ws2[(d4 + 1) * 256 + t];
            float u2 = ws1[(d4 + 2) * 256 + t], v2 = ws2[(d4 + 2) * 256 + t];
            float u3 = ws1[(d4 + 3) * 256 + t], v3 = ws2[(d4 + 3) * 256 + t];
#pragma unroll
            for (int r = 0; r < 4; ++r) {
                const float4 xv = *reinterpret_cast<const float4*>(&xs[r * 256 + dt * 32 + d4]);
                a1[r] = fmaf(xv.x, u0, a1[r]); a2[r] = fmaf(xv.x, v0, a2[r]);
                a1[r] = fmaf(xv.y, u1, a1[r]); a2[r] = fmaf(xv.y, v1, a2[r]);
                a1[r] = fmaf(xv.z, u2, a1[r]); a2[r] = fmaf(xv.z, v2, a2[r]);
                a1[r] = fmaf(xv.w, u3, a1[r]); a2[r] = fmaf(xv.w, v3, a2[r]);
            }
        }
    }
#pragma unroll
    for (int r = 0; r < 4; ++r) {
        const int row = r0 + r;
        xi1[row * 256 + t] = a1[r];
        c1[row * 256 + t]  = __float2half_rn(a2[r] + __ldg(&bias_h1[(row & (PN - 1)) * 256 + t]));
    }
}

// ---------------------------------------------------------------------------
// Final: out = relu((A + B) @ W). 4 rows/block, grid = 256.
// ---------------------------------------------------------------------------
__global__ __launch_bounds__(256) void rowgemm4_sum_kernel(
    const float* __restrict__ A, const float* __restrict__ B,
    const float* __restrict__ W, float* __restrict__ out)
{
    __shared__ float xs[4 * 256];
    __shared__ float ws[32 * 256];
    const int r0 = blockIdx.x * 4;
    const int t  = threadIdx.x;
    for (int f = t; f < 4 * 256; f += 256) xs[f] = A[r0 * 256 + f] + B[r0 * 256 + f];

    float acc[4] = {0.f, 0.f, 0.f, 0.f};

    for (int dt = 0; dt < 8; ++dt) {
        __syncthreads();
        const float4* Wv = reinterpret_cast<const float4*>(W + dt * 32 * 256);
        float4* wsv = reinterpret_cast<float4*>(ws);
        for (int i = t; i < 2048; i += 256) wsv[i] = __ldg(&Wv[i]);
        __syncthreads();
#pragma unroll
        for (int d4 = 0; d4 < 32; d4 += 4) {
            float wv0 = ws[(d4 + 0) * 256 + t];
            float wv1 = ws[(d4 + 1) * 256 + t];
            float wv2 = ws[(d4 + 2) * 256 + t];
            float wv3 = ws[(d4 + 3) * 256 + t];
#pragma unroll
            for (int r = 0; r < 4; ++r) {
                const float4 xv = *reinterpret_cast<const float4*>(&xs[r * 256 + dt * 32 + d4]);
                acc[r] = fmaf(xv.x, wv0, acc[r]);
                acc[r] = fmaf(xv.y, wv1, acc[r]);
                acc[r] = fmaf(xv.z, wv2, acc[r]);
                acc[r] = fmaf(xv.w, wv3, acc[r]);
            }
        }
    }
#pragma unroll
    for (int r = 0; r < 4; ++r) out[(r0 + r) * 256 + t] = fmaxf(acc[r], 0.f);
}

// ---------------------------------------------------------------------------
// Fused graph-learning kernel (round-13 proven version).
// ---------------------------------------------------------------------------
__global__ void pair_softadj_kernel(const float* __restrict__ xhat,
                                    const float* __restrict__ adj,
                                    const float* __restrict__ learn_w,
                                    const int*   __restrict__ box_num,
                                    float* __restrict__ soft_adj_out,
                                    float* __restrict__ adj2,
                                    float* __restrict__ pair_norm)
{
    const int row = blockIdx.x;
    const int b = row >> 8;
    const int i = row & 255;
    const int t = threadIdx.x;
    const int warp = t >> 5, lane = t & 31;

    __shared__ float xi_s[128];
    __shared__ float w_s[128];
    __shared__ float sval[256];
    __shared__ float red[256];
    __shared__ float wsum_s, rmax_s;

    if (t < 128) { xi_s[t] = xhat[row * 128 + t]; w_s[t] = learn_w[t]; }
    __syncthreads();
    if (t == 0) {
        float s = 0.f;
        for (int d = 0; d < 128; ++d) s += w_s[d];
        wsum_s = s;
    }
    __syncthreads();

    const int bn = box_num[b];
    const bool vi = (i < bn);
    const float wsum = wsum_s;
    const float4 xi4 = reinterpret_cast<const float4*>(xi_s)[lane];
    const float4 w4  = reinterpret_cast<const float4*>(w_s)[lane];

    for (int j = warp; j < 256; j += 8) {
        const float4 xj4 = __ldg(reinterpret_cast<const float4*>(xhat + (b * 256 + j) * 128) + lane);
        const float d0 = xi4.x - xj4.x, d1 = xi4.y - xj4.y;
        const float d2 = xi4.z - xj4.z, d3 = xi4.w - xj4.w;
        float s = fabsf(d0) * w4.x + fabsf(d1) * w4.y + fabsf(d2) * w4.z + fabsf(d3) * w4.w;
        float q = d0 * d0 + d1 * d1 + d2 * d2 + d3 * d3;
#pragma unroll
        for (int off = 16; off; off >>= 1) {
            s += __shfl_down_sync(0xffffffffu, s, off);
            q += __shfl_down_sync(0xffffffffu, q, off);
        }
        if (lane == 0) {
            const float m = (vi && (j < bn)) ? 0.f : -1.f;
            float v = s + m * wsum;
            v = (v > 0.f) ? v : 0.01f * v;
            sval[j] = v;
            pair_norm[row * 256 + j] = sqrtf(q + 1e-12f);
        }
    }
    __syncthreads();

    const float v = sval[t];
    red[t] = v;
    __syncthreads();
    for (int sft = 128; sft; sft >>= 1) {
        if (t < sft) red[t] = fmaxf(red[t], red[t + sft]);
        __syncthreads();
    }
    if (t == 0) rmax_s = red[0];
    __syncthreads();

    const float a = adj[row * 256 + t];
    const float e = expf(v - rmax_s) * a;
    red[t] = e;
    __syncthreads();
    for (int sft = 128; sft; sft >>= 1) {
        if (t < sft) red[t] += red[t + sft];
        __syncthreads();
    }
    const float sa = e / red[0] + 1e-10f;
    soft_adj_out[row * 256 + t] = sa;
    adj2[row * 256 + t] = a * sa;
}

// ---------------------------------------------------------------------------
// gl_loss two-phase reduction.
// ---------------------------------------------------------------------------
__global__ void glloss_part_kernel(const float* __restrict__ soft_adj,
                                   const float* __restrict__ pair_norm)
{
    const int blk = blockIdx.x;
    const int b = blk >> 7;
    const int t = threadIdx.x;
    const int base = b * 65536 + (blk & 127) * 512;
    float s1 = 0.f, s2 = 0.f;
#pragma unroll
    for (int u = 0; u < 2; ++u) {
        const int idx = base + u * 256 + t;
        const float s = soft_adj[idx];
        s1 += expf(s + pair_norm[idx]);
        s2 += s * s;
    }
    __shared__ float r1[256], r2[256];
    r1[t] = s1; r2[t] = s2;
    __syncthreads();
    for (int sft = 128; sft; sft >>= 1) {
        if (t < sft) { r1[t] += r1[t + sft]; r2[t] += r2[t + sft]; }
        __syncthreads();
    }
    if (t == 0) { g_part1[blk] = r1[0]; g_part2[blk] = r2[0]; }
}

__global__ void glloss_fin_kernel(const int* __restrict__ box_num, float* __restrict__ gl_out)
{
    const int b = blockIdx.x;
    const int t = threadIdx.x;
    __shared__ float r1[128], r2[128];
    r1[t] = g_part1[b * 128 + t];
    r2[t] = g_part2[b * 128 + t];
    __syncthreads();
    for (int sft = 64; sft; sft >>= 1) {
        if (t < sft) { r1[t] += r1[t + sft]; r2[t] += r2[t + sft]; }
        __syncthreads();
    }
    if (t == 0) {
        const float bnf = (float)box_num[b];
        gl_out[b] = r1[0] / (bnf * bnf) + 1e-4f * sqrtf(r2[0]);
    }
}

// ---------------------------------------------------------------------------
// Kernel A: AH0 only (round-13 proven version). c0 fp16, MLP=8.
// ---------------------------------------------------------------------------
__global__ __launch_bounds__(256) void ah0_kernel(
    const float* __restrict__ xi0, const __half* __restrict__ c0,
    const float* __restrict__ rel, const float* __restrict__ Wt,
    const float* __restrict__ adj2, float* __restrict__ AH0)
{
    __shared__ __align__(16) float rel_s[1536];
    __shared__ __align__(16) float wt_s[1536];
    __shared__ __align__(16) float adj_s[256];
    __shared__ __align__(16) float ahred[2048];
    __shared__ __align__(16) float xi_s[256];

    const int t = threadIdx.x;
    const int wid = t >> 5;
    const int lane = t & 31;
    const int row = blockIdx.x;
    const int b = row >> 8;

    const float* relrow = rel + (size_t)row * 256 * 6;
    for (int f = t; f < 1536; f += 256) { rel_s[f] = relrow[f]; wt_s[f] = Wt[f]; }
    adj_s[t] = adj2[row * 256 + t];
    xi_s[t]  = xi0[row * 256 + t];
    __syncthreads();

    const uint2* c0q = reinterpret_cast<const uint2*>(c0 + b * 65536);

#pragma unroll
    for (int kq2 = 0; kq2 < 2; ++kq2) {
        const int q = lane + 32 * kq2;
        const ulonglong2 xiv = *reinterpret_cast<const ulonglong2*>(&xi_s[4 * q]);
        ull_t wt2[6][2];
#pragma unroll
        for (int c = 0; c < 6; ++c) {
            const ulonglong2 w = *reinterpret_cast<const ulonglong2*>(&wt_s[c * 256 + 4 * q]);
            wt2[c][0] = w.x; wt2[c][1] = w.y;
        }

        float ah0 = 0.f, ah1 = 0.f, ah2 = 0.f, ah3 = 0.f;
#pragma unroll 1
        for (int s = 0; s < 32; s += 8) {
            uint2 cv[8];
#pragma unroll
            for (int u = 0; u < 8; ++u)
                cv[u] = __ldg(&c0q[(wid * 32 + s + u) * 64 + q]);
#pragma unroll
            for (int u = 0; u < 8; ++u) {
                const int j = wid * 32 + s + u;
                const float* rj = rel_s + j * 6;
                ull_t t0 = add2(xiv.x, h2_to_pk(cv[u].x));
                ull_t t1 = add2(xiv.y, h2_to_pk(cv[u].y));
#pragma unroll
                for (int c = 0; c < 6; ++c) {
                    const ull_t rp = pk2(rj[c], rj[c]);
                    t0 = fma2(rp, wt2[c][0], t0);
                    t1 = fma2(rp, wt2[c][1], t1);
                }
                float h0, h1, h2, h3;
                upk2(t0, h0, h1);
                upk2(t1, h2, h3);
                const float aw = adj_s[j];
                ah0 = fmaf(aw, fmaxf(h0, 0.f), ah0);
                ah1 = fmaf(aw, fmaxf(h1, 0.f), ah1);
                ah2 = fmaf(aw, fmaxf(h2, 0.f), ah2);
                ah3 = fmaf(aw, fmaxf(h3, 0.f), ah3);
            }
        }
        float4 o; o.x = ah0; o.y = ah1; o.z = ah2; o.w = ah3;
        *reinterpret_cast<float4*>(&ahred[wid * 256 + 4 * q]) = o;
    }
    __syncthreads();

    float s = 0.f;
#pragma unroll
    for (int g = 0; g < 8; ++g) s += ahred[g * 256 + t];
    AH0[row * 256 + t] = s;
}

// ---------------------------------------------------------------------------
// Kernel C: fused layer0 GEMM + layer1 reduction (round-13 proven version).
// ---------------------------------------------------------------------------
// SMEM byte offsets
#define SM_A       0         // 128 j x 256 k fp16, 512B rows, xor-swizzled = 65536
#define SM_B1      65536     // 32768
#define SM_REL     98304     // 3072
#define SM_ADJ     101376    // 1024
#define SM_AHRED   102400    // 8192 (8 warps x 256 n)
#define SM_XI      110592    // 1024
#define SM_XI1     111616    // 1024
#define SM_TOTAL   112640

__global__ void __launch_bounds__(256, 2) layer01_mma_kernel(
    const float* __restrict__ xi0, const __half* __restrict__ c0,
    const float* __restrict__ rel, const float* __restrict__ Wt,
    const float* __restrict__ adj2,
    const float* __restrict__ xi1, const __half* __restrict__ c1,
    float* __restrict__ AH1a, float* __restrict__ AH1b)
{
    extern __shared__ char sm[];
    const uint32_t sb = smem_to_u32(sm);
    float* rel_s  = reinterpret_cast<float*>(sm + SM_REL);
    float* adj_s  = reinterpret_cast<float*>(sm + SM_ADJ);
    float* ah1red = reinterpret_cast<float*>(sm + SM_AHRED);
    float* xi_s   = reinterpret_cast<float*>(sm + SM_XI);
    float* xi1_s  = reinterpret_cast<float*>(sm + SM_XI1);

    const int t = threadIdx.x;
    const int wid = t >> 5;
    const int lane = t & 31;
    const int row = blockIdx.x;      // b*256 + i
    const int jh  = blockIdx.y;      // 0 or 1
    const int b = row >> 8;

    adj_s[t]  = adj2[row * 256 + t];
    xi_s[t]   = xi0[row * 256 + t];
    xi1_s[t]  = xi1[row * 256 + t];
    const float* relrow = rel + ((size_t)row * 256 + jh * 128) * 6;
    for (int f = t; f < 768; f += 256) rel_s[f] = relrow[f];
    __syncthreads();

    const uint2* c0q = reinterpret_cast<const uint2*>(c0 + b * 65536);
    const __half* c1b = c1 + b * 65536;

    // --- per-lane ldmatrix address components ---
    const int jrl = wid * 16 + (lane & 15);
    const uint32_t acolByte = (uint32_t)((lane >> 4) * 16);
    const uint32_t jmask = (uint32_t)((jrl & 7) << 4);
    const uint32_t aRowByte = (uint32_t)jrl * 512u;
    const int nrow_l = (lane & 7) | ((lane & 16) >> 1);
    const uint32_t kbB = (uint32_t)(((lane >> 3) & 1) * 16);
    const uint32_t nmask = (uint32_t)((nrow_l & 7) << 4);
    const uint32_t bRowByte = (uint32_t)nrow_l * 256u;

    const int r  = lane >> 2;    // 0..7
    const int cq = lane & 3;     // 0..3

    // ---- build H half (128 j x 256 k) as fp16; 4 k per iter, MLP=4 ----
#pragma unroll
    for (int kq2 = 0; kq2 < 2; ++kq2) {
        const int q = lane + 32 * kq2;     // k-quad 0..63
        const ulonglong2 xiv = *reinterpret_cast<const ulonglong2*>(&xi_s[4 * q]);
        ull_t wt2[6][2];
#pragma unroll
        for (int c = 0; c < 6; ++c) {
            const float2 wa = __ldg(reinterpret_cast<const float2*>(&Wt[c * 256 + 4 * q]));
            const float2 wb = __ldg(reinterpret_cast<const float2*>(&Wt[c * 256 + 4 * q + 2]));
            wt2[c][0] = pk2(wa.x, wa.y);
            wt2[c][1] = pk2(wb.x, wb.y);
        }

#pragma unroll 1
        for (int s = 0; s < 16; s += 4) {
            uint2 cv[4];
#pragma unroll
            for (int u = 0; u < 4; ++u) {
                const int j = jh * 128 + wid * 16 + s + u;
                cv[u] = __ldg(&c0q[j * 64 + q]);
            }
#pragma unroll
            for (int u = 0; u < 4; ++u) {
                const int jl = wid * 16 + s + u;
                const float* rj = rel_s + jl * 6;
                ull_t t0 = add2(xiv.x, h2_to_pk(cv[u].x));
                ull_t t1 = add2(xiv.y, h2_to_pk(cv[u].y));
#pragma unroll
                for (int c = 0; c < 6; ++c) {
                    const ull_t rp = pk2(rj[c], rj[c]);
                    t0 = fma2(rp, wt2[c][0], t0);
                    t1 = fma2(rp, wt2[c][1], t1);
                }
                float h0, h1, h2, h3;
                upk2(t0, h0, h1);
                upk2(t1, h2, h3);
                __half2 ha = __floats2half2_rn(fmaxf(h0, 0.f), fmaxf(h1, 0.f));
                __half2 hb = __floats2half2_rn(fmaxf(h2, 0.f), fmaxf(h3, 0.f));
                uint2 hv;
                hv.x = *reinterpret_cast<uint32_t*>(&ha);
                hv.y = *reinterpret_cast<uint32_t*>(&hb);
                const uint32_t off = (uint32_t)jl * 512u + ((uint32_t)(8 * q) ^ ((uint32_t)(jl & 7) << 4));
                *reinterpret_cast<uint2*>(sm + SM_A + off) = hv;
            }
        }
    }

#pragma unroll 1
    for (int nc = 0; nc < 2; ++nc) {
        float C[16][4];
#pragma unroll
        for (int nt = 0; nt < 16; ++nt)
#pragma unroll
            for (int u = 0; u < 4; ++u) C[nt][u] = 0.f;

#pragma unroll 1
        for (int kh = 0; kh < 2; ++kh) {
            __syncthreads();   // prior B consumers done (first iter: A build visibility)
            {
                const uint4* s1 = reinterpret_cast<const uint4*>(
                    reinterpret_cast<const char*>(g_wimg1) + kh * 65536 + nc * 32768);
                uint4* d1 = reinterpret_cast<uint4*>(sm + SM_B1);
                for (int i = t; i < 2048; i += 256) d1[i] = __ldg(&s1[i]);
            }
            __syncthreads();

            // ---- HMMA: C += A * B ----
#pragma unroll 1
            for (int ks = 0; ks < 8; ++ks) {
                const uint32_t aoff = ((uint32_t)((kh * 8 + ks) * 32) + acolByte) ^ jmask;
                const uint32_t boff = ((uint32_t)(ks * 32) + kbB) ^ nmask;
                uint32_t Ah[4];
                ldsm4(Ah, sb + SM_A + aRowByte + aoff);

                uint32_t bb[4];
#pragma unroll
                for (int p = 0; p < 8; ++p) {
                    ldsm4(bb, sb + SM_B1 + (uint32_t)p * 4096 + bRowByte + boff);
                    mma_f16(C[2 * p],     Ah, bb[0], bb[1]);
                    mma_f16(C[2 * p + 1], Ah, bb[2], bb[3]);
                }
            }
        }

        // ---- fused layer1 epilogue: consume alpha1 = relu(C) in registers ----
        {
            float acc0[16], acc1[16];
#pragma unroll
            for (int nt = 0; nt < 16; ++nt) { acc0[nt] = 0.f; acc1[nt] = 0.f; }

            const int j1 = jh * 128 + wid * 16 + r;
            const int j2 = j1 + 8;
            const float aw1 = adj_s[j1];
            const float aw2 = adj_s[j2];

#pragma unroll
            for (int ntb = 0; ntb < 16; ntb += 4) {
                uint32_t cA[4], cB[4];
#pragma unroll
                for (int u = 0; u < 4; ++u) {
                    const int n0 = nc * 128 + (ntb + u) * 8 + 2 * cq;
                    cA[u] = __ldg(reinterpret_cast<const uint32_t*>(c1b + j1 * 256 + n0));
                    cB[u] = __ldg(reinterpret_cast<const uint32_t*>(c1b + j2 * 256 + n0));
                }
#pragma unroll
                for (int u = 0; u < 4; ++u) {
                    const int nt = ntb + u;
                    const int n0 = nc * 128 + nt * 8 + 2 * cq;
                    const float2 fA = __half22float2(*reinterpret_cast<const __half2*>(&cA[u]));
                    const float2 fB = __half22float2(*reinterpret_cast<const __half2*>(&cB[u]));
                    const float x0 = xi1_s[n0];
                    const float x1v = xi1_s[n0 + 1];
                    const float a0 = fmaxf(C[nt][0], 0.f);
                    const float a1 = fmaxf(C[nt][1], 0.f);
                    const float a2 = fmaxf(C[nt][2], 0.f);
                    const float a3 = fmaxf(C[nt][3], 0.f);
                    acc0[nt] = fmaf(aw1, fmaxf(x0 + fA.x + a0, 0.f), acc0[nt]);
                    acc1[nt] = fmaf(aw1, fmaxf(x1v + fA.y + a1, 0.f), acc1[nt]);
                    acc0[nt] = fmaf(aw2, fmaxf(x0 + fB.x + a2, 0.f), acc0[nt]);
                    acc1[nt] = fmaf(aw2, fmaxf(x1v + fB.y + a3, 0.f), acc1[nt]);
                }
            }

#pragma unroll
            for (int nt = 0; nt < 16; ++nt) {
                float v0 = acc0[nt], v1 = acc1[nt];
#pragma unroll
                for (int off = 4; off <= 16; off <<= 1) {
                    v0 += __shfl_xor_sync(0xffffffffu, v0, off);
                    v1 += __shfl_xor_sync(0xffffffffu, v1, off);
                }
                if (r == 0) {
                    const int n0 = nc * 128 + nt * 8 + 2 * cq;
                    ah1red[wid * 256 + n0]     = v0;
                    ah1red[wid * 256 + n0 + 1] = v1;
                }
            }
        }
    }
    __syncthreads();

    // cross-warp reduce -> AH1part[jh]
    {
        float s = 0.f;
#pragma unroll
        for (int g = 0; g < 8; ++g) s += ah1red[g * 256 + t];
        float* dst = jh ? AH1b : AH1a;
        dst[row * 256 + t] = s;
    }
}

// ---------------------------------------------------------------------------
extern "C" void kernel_launch(void* const* d_in, const int* in_sizes, int n_in,
                              void* d_out, int out_size)
{
    (void)in_sizes; (void)n_in; (void)out_size;

    const float* x        = (const float*)d_in[0];
    const float* rel      = (const float*)d_in[1];
    const float* adj      = (const float*)d_in[2];
    const int*   bnum     = (const int*)  d_in[3];
    const float* Wt       = (const float*)d_in[4];
    const float* b_alpha  = (const float*)d_in[5];
    const float* W_proj   = (const float*)d_in[6];
    const float* b_proj   = (const float*)d_in[7];
    const float* learn_w  = (const float*)d_in[8];
    const float* w_alpha0 = (const float*)d_in[9];
    const float* w_vi0    = (const float*)d_in[10];
    const float* w_vj0    = (const float*)d_in[11];
    const float* bias_h0  = (const float*)d_in[12];
    const float* w_node0  = (const float*)d_in[13];
    /* d_in[14] = l1_w_alpha: unused (alpha2 discarded) */
    const float* w_vi1    = (const float*)d_in[15];
    const float* w_vj1    = (const float*)d_in[16];
    const float* bias_h1  = (const float*)d_in[17];
    const float* w_node1  = (const float*)d_in[18];

    float* out      = (float*)d_out;
    float* out_x2   = out;
    float* out_sadj = out + 262144;
    float* out_gl   = out + 524288;

    float *xhat, *pnorm, *adj2, *xi0, *AH0, *xi1, *AH1a, *AH1b;
    __half *c0, *c1;
    cudaGetSymbolAddress((void**)&xhat,  g_xhat);
    cudaGetSymbolAddress((void**)&pnorm, g_pnorm);
    cudaGetSymbolAddress((void**)&adj2,  g_adj2);
    cudaGetSymbolAddress((void**)&xi0,   g_xi0);
    cudaGetSymbolAddress((void**)&c0,    g_c0);
    cudaGetSymbolAddress((void**)&AH0,   g_AH0);
    cudaGetSymbolAddress((void**)&xi1,   g_xi1);
    cudaGetSymbolAddress((void**)&c1,    g_c1);
    cudaGetSymbolAddress((void**)&AH1a,  g_AH1a);
    cudaGetSymbolAddress((void**)&AH1b,  g_AH1b);

    const int DUAL_SMEM = (1024 + 8192 + 8192) * 4;   // 69632 B

    cudaFuncSetAttribute(rowgemm4_dual_prep_kernel, cudaFuncAttributeMaxDynamicSharedMemorySize, DUAL_SMEM);
    rowgemm4_dual_prep_kernel<<<256, 256, DUAL_SMEM>>>(x, w_vi0, w_vj0, bias_h0, b_alpha, w_alpha0, xi0, c0);

    rowgemm_kernel<<<256, 128>>>(x, W_proj, b_proj, xhat);
    pair_softadj_kernel<<<1024, 256>>>(xhat, adj, learn_w, bnum, out_sadj, adj2, pnorm);

    ah0_kernel<<<1024, 256>>>(xi0, c0, rel, Wt, adj2, AH0);
    cudaFuncSetAttribute(chain_kernel, cudaFuncAttributeMaxDynamicSharedMemorySize, DUAL_SMEM);
    chain_kernel<<<256, 256, DUAL_SMEM>>>(AH0, w_node0, w_vi1, w_vj1, bias_h1, xi1, c1);

    cudaFuncSetAttribute(layer01_mma_kernel, cudaFuncAttributeMaxDynamicSharedMemorySize, SM_TOTAL);
    layer01_mma_kernel<<<dim3(1024, 2), 256, SM_TOTAL>>>(xi0, c0, rel, Wt, adj2, xi1, c1, AH1a, AH1b);

    glloss_part_kernel<<<512, 256>>>(out_sadj, pnorm);
    glloss_fin_kernel<<<4, 128>>>(bnum, out_gl);
    rowgemm4_sum_kernel<<<256, 256>>>(AH1a, AH1b, w_node1, out_x2);
}

// round 16
// speedup vs baseline: 1.0653x; 1.0383x over previous
#include <cuda_runtime.h>
#include <cuda_fp16.h>
#include <cstdint>
#include <cstddef>

// Problem constants
#define PB 4
#define PN 256
#define PD 256
#define PL 128
#define POUT 256

// ============================ helpers ============================
__device__ __forceinline__ uint32_t smem_to_u32(const void* smem_ptr) {
    uint32_t addr;
    asm("{ .reg .u64 tmp; cvta.to.shared.u64 tmp, %1; cvt.u32.u64 %0, tmp; }"
        : "=r"(addr) : "l"(smem_ptr));
    return addr;
}

__device__ __forceinline__ void ldsm4(uint32_t* r, uint32_t addr) {
    asm volatile("ldmatrix.sync.aligned.m8n8.x4.shared.b16 {%0,%1,%2,%3}, [%4];"
        : "=r"(r[0]), "=r"(r[1]), "=r"(r[2]), "=r"(r[3]) : "r"(addr));
}

__device__ __forceinline__ void mma_f16(float* c, const uint32_t* a, uint32_t b0, uint32_t b1) {
    asm volatile(
        "mma.sync.aligned.m16n8k16.row.col.f32.f16.f16.f32 "
        "{%0,%1,%2,%3}, {%4,%5,%6,%7}, {%8,%9}, {%0,%1,%2,%3};"
        : "+f"(c[0]), "+f"(c[1]), "+f"(c[2]), "+f"(c[3])
        : "r"(a[0]), "r"(a[1]), "r"(a[2]), "r"(a[3]), "r"(b0), "r"(b1));
}

// ---- packed f32x2 ops (sm_100+ baseline PTX) ----
typedef unsigned long long ull_t;
__device__ __forceinline__ ull_t pk2(float lo, float hi) {
    ull_t r;
    asm("mov.b64 %0, {%1, %2};" : "=l"(r)
        : "r"(__float_as_uint(lo)), "r"(__float_as_uint(hi)));
    return r;
}
__device__ __forceinline__ void upk2(ull_t v, float& lo, float& hi) {
    uint32_t a, b;
    asm("mov.b64 {%0, %1}, %2;" : "=r"(a), "=r"(b) : "l"(v));
    lo = __uint_as_float(a); hi = __uint_as_float(b);
}
__device__ __forceinline__ ull_t fma2(ull_t a, ull_t b, ull_t c) {
    ull_t d;
    asm("fma.rn.f32x2 %0, %1, %2, %3;" : "=l"(d) : "l"(a), "l"(b), "l"(c));
    return d;
}
__device__ __forceinline__ ull_t add2(ull_t a, ull_t b) {
    ull_t d;
    asm("add.rn.f32x2 %0, %1, %2;" : "=l"(d) : "l"(a), "l"(b));
    return d;
}
__device__ __forceinline__ ull_t h2_to_pk(uint32_t h2bits) {
    const __half2 h = *reinterpret_cast<const __half2*>(&h2bits);
    const float2 f = __half22float2(h);
    return pk2(f.x, f.y);
}

// ---- cp.async staging (sm_80+ baseline) ----
__device__ __forceinline__ void stage_tile(float* buf, const float* W, int t) {
    const uint32_t dst = smem_to_u32(buf);
    const char* src = reinterpret_cast<const char*>(W);
#pragma unroll
    for (int i = t; i < 2048; i += 256)
        asm volatile("cp.async.ca.shared.global [%0], [%1], 16;"
            :: "r"(dst + (uint32_t)i * 16), "l"(src + (size_t)i * 16));
}
#define CP_COMMIT() asm volatile("cp.async.commit_group;" ::: "memory")
#define CP_WAIT0()  asm volatile("cp.async.wait_group 0;" ::: "memory")

// ---------------- scratch (device globals; no runtime allocation) ----------------
__device__ float g_xhat [PB*PN*PL];
__device__ float g_pnorm[PB*PN*PN];
__device__ float g_adj2 [PB*PN*PN];
__device__ float g_xi0  [PB*PN*POUT];
__device__ __half g_c0  [PB*PN*POUT];   // fp16 pair-constant (layer 0)
__device__ float g_AH0  [PB*PN*POUT];
__device__ float g_xi1  [PB*PN*POUT];
__device__ __half g_c1  [PB*PN*POUT];   // fp16 pair-constant (layer 1)
__device__ float g_AH1a [PB*PN*POUT];
__device__ float g_AH1b [PB*PN*POUT];
__device__ float g_part1[512];
__device__ float g_part2[512];
// Pre-converted w_alpha image: [kh:2][n:256][k:128] fp16, 256B rows,
// XOR-swizzled by (n&7)<<4 -> ldmatrix conflict-free, verbatim staging.
// kh stride = 65536 BYTES.
__device__ __half g_wimg1[2*256*128];

// ---------------------------------------------------------------------------
// Simple row GEMM for xhat (K=128)
// ---------------------------------------------------------------------------
__global__ void rowgemm_kernel(const float* __restrict__ X, const float* __restrict__ W,
                               const float* __restrict__ bias_k, float* __restrict__ out)
{
    __shared__ float xs[4 * 256];
    const int r0 = blockIdx.x * 4;
    const int t  = threadIdx.x;
    for (int f = t; f < 4 * 256; f += 128) xs[f] = X[r0 * 256 + f];
    __syncthreads();

    float acc[4] = {0.f, 0.f, 0.f, 0.f};
#pragma unroll 8
    for (int d = 0; d < 256; ++d) {
        const float wv = __ldg(&W[d * 128 + t]);
#pragma unroll
        for (int r = 0; r < 4; ++r) acc[r] = fmaf(xs[r * 256 + d], wv, acc[r]);
    }
    const float bk = __ldg(&bias_k[t]);
#pragma unroll
    for (int r = 0; r < 4; ++r) out[(r0 + r) * 128 + t] = acc[r] + bk;
}

// ---------------------------------------------------------------------------
// Dual row GEMM (layer-0 inputs) + FUSED w_alpha image prep.
// 8 rows/block, grid 128; cp.async double-buffered W staging.
// ---------------------------------------------------------------------------
__global__ __launch_bounds__(256) void rowgemm8_dual_prep_kernel(
    const float* __restrict__ X, const float* __restrict__ W1, const float* __restrict__ W2,
    const float* __restrict__ bias_nk, const float* __restrict__ bias_k,
    const float* __restrict__ w_alpha,
    float* __restrict__ out1, __half* __restrict__ out2)
{
    extern __shared__ float dsm[];
    float* xs  = dsm;                       // 2048
    float* wbuf[4] = { dsm + 2048, dsm + 10240, dsm + 18432, dsm + 26624 };   // 4 x 8192
    const int r0 = blockIdx.x * 8;
    const int t  = threadIdx.x;

    // ---- fused prep: convert w_alpha (k=d:256, n:256) into fp16 transposed image ----
    {
        const int base = (blockIdx.x * 256 + t) * 2;
#pragma unroll
        for (int u = 0; u < 2; ++u) {
            const int e = base + u;
            const int k = e >> 8;
            const int n = e & 255;
            const __half hi = __float2half_rn(__ldg(&w_alpha[k * 256 + n]));
            const int kh = k >> 7, kk = k & 127;
            const uint32_t off = kh * 65536u + n * 256u + (uint32_t)((kk * 2) ^ ((n & 7) << 4));
            *reinterpret_cast<__half*>(reinterpret_cast<char*>(g_wimg1) + off) = hi;
        }
    }

    for (int f = t; f < 8 * 256; f += 256) xs[f] = X[r0 * 256 + f];

    float a1[8], a2[8];
#pragma unroll
    for (int r = 0; r < 8; ++r) { a1[r] = 0.f; a2[r] = 0.f; }

    stage_tile(wbuf[0], W1, t);
    stage_tile(wbuf[2], W2, t);
    CP_COMMIT();

    for (int dt = 0; dt < 8; ++dt) {
        CP_WAIT0();
        __syncthreads();
        if (dt < 7) {
            stage_tile(wbuf[(dt + 1) & 1],     W1 + (dt + 1) * 8192, t);
            stage_tile(wbuf[2 + ((dt + 1) & 1)], W2 + (dt + 1) * 8192, t);
            CP_COMMIT();
        }
        const float* ws1 = wbuf[dt & 1];
        const float* ws2 = wbuf[2 + (dt & 1)];
#pragma unroll
        for (int d4 = 0; d4 < 32; d4 += 4) {
            float u0 = ws1[(d4 + 0) * 256 + t], v0 = ws2[(d4 + 0) * 256 + t];
            float u1 = ws1[(d4 + 1) * 256 + t], v1 = ws2[(d4 + 1) * 256 + t];
            float u2 = ws1[(d4 + 2) * 256 + t], v2 = ws2[(d4 + 2) * 256 + t];
            float u3 = ws1[(d4 + 3) * 256 + t], v3 = ws2[(d4 + 3) * 256 + t];
#pragma unroll
            for (int r = 0; r < 8; ++r) {
                const float4 xv = *reinterpret_cast<const float4*>(&xs[r * 256 + dt * 32 + d4]);
                a1[r] = fmaf(xv.x, u0, a1[r]); a2[r] = fmaf(xv.x, v0, a2[r]);
                a1[r] = fmaf(xv.y, u1, a1[r]); a2[r] = fmaf(xv.y, v1, a2[r]);
                a1[r] = fmaf(xv.z, u2, a1[r]); a2[r] = fmaf(xv.z, v2, a2[r]);
                a1[r] = fmaf(xv.w, u3, a1[r]); a2[r] = fmaf(xv.w, v3, a2[r]);
            }
        }
        __syncthreads();
    }
    const float bk = bias_k ? __ldg(&bias_k[t]) : 0.f;
#pragma unroll
    for (int r = 0; r < 8; ++r) {
        const int row = r0 + r;
        out1[row * 256 + t] = a1[r];
        out2[row * 256 + t] = __float2half_rn(a2[r] + bk + __ldg(&bias_nk[(row & (PN - 1)) * 256 + t]));
    }
}

// ---------------------------------------------------------------------------
// Fused chain: x1 = relu(AH0 @ Wn0); xi1 = x1 @ Wvi1; c1 = fp16(x1 @ Wvj1 + bias_h1).
// cp.async double-buffered.
// ---------------------------------------------------------------------------
__global__ __launch_bounds__(256) void chain_kernel(
    const float* __restrict__ AH0, const float* __restrict__ Wn0,
    const float* __restrict__ Wvi1, const float* __restrict__ Wvj1,
    const float* __restrict__ bias_h1,
    float* __restrict__ xi1, __half* __restrict__ c1)
{
    extern __shared__ float dsm[];
    float* xs  = dsm;                       // 2048
    float* wbuf[4] = { dsm + 2048, dsm + 10240, dsm + 18432, dsm + 26624 };
    const int r0 = blockIdx.x * 8;
    const int t  = threadIdx.x;
    for (int f = t; f < 8 * 256; f += 256) xs[f] = AH0[r0 * 256 + f];

    // ---- phase 1: x1 = relu(AH0 @ Wn0) ----
    float acc[8];
#pragma unroll
    for (int r = 0; r < 8; ++r) acc[r] = 0.f;

    stage_tile(wbuf[0], Wn0, t);
    CP_COMMIT();

    for (int dt = 0; dt < 8; ++dt) {
        CP_WAIT0();
        __syncthreads();
        if (dt < 7) {
            stage_tile(wbuf[(dt + 1) & 1], Wn0 + (dt + 1) * 8192, t);
            CP_COMMIT();
        }
        const float* ws = wbuf[dt & 1];
#pragma unroll
        for (int d4 = 0; d4 < 32; d4 += 4) {
            float wv0 = ws[(d4 + 0) * 256 + t];
            float wv1 = ws[(d4 + 1) * 256 + t];
            float wv2 = ws[(d4 + 2) * 256 + t];
            float wv3 = ws[(d4 + 3) * 256 + t];
#pragma unroll
            for (int r = 0; r < 8; ++r) {
                const float4 xv = *reinterpret_cast<const float4*>(&xs[r * 256 + dt * 32 + d4]);
                acc[r] = fmaf(xv.x, wv0, acc[r]);
                acc[r] = fmaf(xv.y, wv1, acc[r]);
                acc[r] = fmaf(xv.z, wv2, acc[r]);
                acc[r] = fmaf(xv.w, wv3, acc[r]);
            }
        }
        __syncthreads();
    }
#pragma unroll
    for (int r = 0; r < 8; ++r) xs[r * 256 + t] = fmaxf(acc[r], 0.f);   // x1 in smem

    // ---- phase 2: xi1 = x1@Wvi1 ; c1 = fp16(x1@Wvj1 + bias_h1) ----
    float a1[8], a2[8];
#pragma unroll
    for (int r = 0; r < 8; ++r) { a1[r] = 0.f; a2[r] = 0.f; }

    stage_tile(wbuf[0], Wvi1, t);
    stage_tile(wbuf[2], Wvj1, t);
    CP_COMMIT();

    for (int dt = 0; dt < 8; ++dt) {
        CP_WAIT0();
        __syncthreads();
        if (dt < 7) {
            stage_tile(wbuf[(dt + 1) & 1],       Wvi1 + (dt + 1) * 8192, t);
            stage_tile(wbuf[2 + ((dt + 1) & 1)], Wvj1 + (dt + 1) * 8192, t);
            CP_COMMIT();
        }
        const float* ws1 = wbuf[dt & 1];
        const float* ws2 = wbuf[2 + (dt & 1)];
#pragma unroll
        for (int d4 = 0; d4 < 32; d4 += 4) {
            float u0 = ws1[(d4 + 0) * 256 + t], v0 = ws2[(d4 + 0) * 256 + t];
            float u1 = ws1[(d4 + 1) * 256 + t], v1 = ws2[(d4 + 1) * 256 + t];
            float u2 = ws1[(d4 + 2) * 256 + t], v2 = ws2[(d4 + 2) * 256 + t];
            float u3 = ws1[(d4 + 3) * 256 + t], v3 = ws2[(d4 + 3) * 256 + t];
#pragma unroll
            for (int r = 0; r < 8; ++r) {
                const float4 xv = *reinterpret_cast<const float4*>(&xs[r * 256 + dt * 32 + d4]);
                a1[r] = fmaf(xv.x, u0, a1[r]); a2[r] = fmaf(xv.x, v0, a2[r]);
                a1[r] = fmaf(xv.y, u1, a1[r]); a2[r] = fmaf(xv.y, v1, a2[r]);
                a1[r] = fmaf(xv.z, u2, a1[r]); a2[r] = fmaf(xv.z, v2, a2[r]);
                a1[r] = fmaf(xv.w, u3, a1[r]); a2[r] = fmaf(xv.w, v3, a2[r]);
            }
        }
        __syncthreads();
    }
#pragma unroll
    for (int r = 0; r < 8; ++r) {
        const int row = r0 + r;
        xi1[row * 256 + t] = a1[r];
        c1[row * 256 + t]  = __float2half_rn(a2[r] + __ldg(&bias_h1[(row & (PN - 1)) * 256 + t]));
    }
}

// ---------------------------------------------------------------------------
// Final: out = relu((A + B) @ W), cp.async double-buffered.
// ---------------------------------------------------------------------------
__global__ __launch_bounds__(256) void rowgemm8_sum_kernel(
    const float* __restrict__ A, const float* __restrict__ B,
    const float* __restrict__ W, float* __restrict__ out)
{
    extern __shared__ float dsm[];
    float* xs = dsm;                        // 2048
    float* wbuf[2] = { dsm + 2048, dsm + 10240 };
    const int r0 = blockIdx.x * 8;
    const int t  = threadIdx.x;
    for (int f = t; f < 8 * 256; f += 256) xs[f] = A[r0 * 256 + f] + B[r0 * 256 + f];

    float acc[8];
#pragma unroll
    for (int r = 0; r < 8; ++r) acc[r] = 0.f;

    stage_tile(wbuf[0], W, t);
    CP_COMMIT();

    for (int dt = 0; dt < 8; ++dt) {
        CP_WAIT0();
        __syncthreads();
        if (dt < 7) {
            stage_tile(wbuf[(dt + 1) & 1], W + (dt + 1) * 8192, t);
            CP_COMMIT();
        }
        const float* ws = wbuf[dt & 1];
#pragma unroll
        for (int d4 = 0; d4 < 32; d4 += 4) {
            float wv0 = ws[(d4 + 0) * 256 + t];
            float wv1 = ws[(d4 + 1) * 256 + t];
            float wv2 = ws[(d4 + 2) * 256 + t];
            float wv3 = ws[(d4 + 3) * 256 + t];
#pragma unroll
            for (int r = 0; r < 8; ++r) {
                const float4 xv = *reinterpret_cast<const float4*>(&xs[r * 256 + dt * 32 + d4]);
                acc[r] = fmaf(xv.x, wv0, acc[r]);
                acc[r] = fmaf(xv.y, wv1, acc[r]);
                acc[r] = fmaf(xv.z, wv2, acc[r]);
                acc[r] = fmaf(xv.w, wv3, acc[r]);
            }
        }
        __syncthreads();
    }
#pragma unroll
    for (int r = 0; r < 8; ++r) out[(r0 + r) * 256 + t] = fmaxf(acc[r], 0.f);
}

// ---------------------------------------------------------------------------
// Fused graph-learning kernel (round-13 proven version).
// ---------------------------------------------------------------------------
__global__ void pair_softadj_kernel(const float* __restrict__ xhat,
                                    const float* __restrict__ adj,
                                    const float* __restrict__ learn_w,
                                    const int*   __restrict__ box_num,
                                    float* __restrict__ soft_adj_out,
                                    float* __restrict__ adj2,
                                    float* __restrict__ pair_norm)
{
    const int row = blockIdx.x;
    const int b = row >> 8;
    const int i = row & 255;
    const int t = threadIdx.x;
    const int warp = t >> 5, lane = t & 31;

    __shared__ float xi_s[128];
    __shared__ float w_s[128];
    __shared__ float sval[256];
    __shared__ float red[256];
    __shared__ float wsum_s, rmax_s;

    if (t < 128) { xi_s[t] = xhat[row * 128 + t]; w_s[t] = learn_w[t]; }
    __syncthreads();
    if (t == 0) {
        float s = 0.f;
        for (int d = 0; d < 128; ++d) s += w_s[d];
        wsum_s = s;
    }
    __syncthreads();

    const int bn = box_num[b];
    const bool vi = (i < bn);
    const float wsum = wsum_s;
    const float4 xi4 = reinterpret_cast<const float4*>(xi_s)[lane];
    const float4 w4  = reinterpret_cast<const float4*>(w_s)[lane];

    for (int j = warp; j < 256; j += 8) {
        const float4 xj4 = __ldg(reinterpret_cast<const float4*>(xhat + (b * 256 + j) * 128) + lane);
        const float d0 = xi4.x - xj4.x, d1 = xi4.y - xj4.y;
        const float d2 = xi4.z - xj4.z, d3 = xi4.w - xj4.w;
        float s = fabsf(d0) * w4.x + fabsf(d1) * w4.y + fabsf(d2) * w4.z + fabsf(d3) * w4.w;
        float q = d0 * d0 + d1 * d1 + d2 * d2 + d3 * d3;
#pragma unroll
        for (int off = 16; off; off >>= 1) {
            s += __shfl_down_sync(0xffffffffu, s, off);
            q += __shfl_down_sync(0xffffffffu, q, off);
        }
        if (lane == 0) {
            const float m = (vi && (j < bn)) ? 0.f : -1.f;
            float v = s + m * wsum;
            v = (v > 0.f) ? v : 0.01f * v;
            sval[j] = v;
            pair_norm[row * 256 + j] = sqrtf(q + 1e-12f);
        }
    }
    __syncthreads();

    const float v = sval[t];
    red[t] = v;
    __syncthreads();
    for (int sft = 128; sft; sft >>= 1) {
        if (t < sft) red[t] = fmaxf(red[t], red[t + sft]);
        __syncthreads();
    }
    if (t == 0) rmax_s = red[0];
    __syncthreads();

    const float a = adj[row * 256 + t];
    const float e = expf(v - rmax_s) * a;
    red[t] = e;
    __syncthreads();
    for (int sft = 128; sft; sft >>= 1) {
        if (t < sft) red[t] += red[t + sft];
        __syncthreads();
    }
    const float sa = e / red[0] + 1e-10f;
    soft_adj_out[row * 256 + t] = sa;
    adj2[row * 256 + t] = a * sa;
}

// ---------------------------------------------------------------------------
// gl_loss two-phase reduction.
// ---------------------------------------------------------------------------
__global__ void glloss_part_kernel(const float* __restrict__ soft_adj,
                                   const float* __restrict__ pair_norm)
{
    const int blk = blockIdx.x;
    const int b = blk >> 7;
    const int t = threadIdx.x;
    const int base = b * 65536 + (blk & 127) * 512;
    float s1 = 0.f, s2 = 0.f;
#pragma unroll
    for (int u = 0; u < 2; ++u) {
        const int idx = base + u * 256 + t;
        const float s = soft_adj[idx];
        s1 += expf(s + pair_norm[idx]);
        s2 += s * s;
    }
    __shared__ float r1[256], r2[256];
    r1[t] = s1; r2[t] = s2;
    __syncthreads();
    for (int sft = 128; sft; sft >>= 1) {
        if (t < sft) { r1[t] += r1[t + sft]; r2[t] += r2[t + sft]; }
        __syncthreads();
    }
    if (t == 0) { g_part1[blk] = r1[0]; g_part2[blk] = r2[0]; }
}

__global__ void glloss_fin_kernel(const int* __restrict__ box_num, float* __restrict__ gl_out)
{
    const int b = blockIdx.x;
    const int t = threadIdx.x;
    __shared__ float r1[128], r2[128];
    r1[t] = g_part1[b * 128 + t];
    r2[t] = g_part2[b * 128 + t];
    __syncthreads();
    for (int sft = 64; sft; sft >>= 1) {
        if (t < sft) { r1[t] += r1[t + sft]; r2[t] += r2[t + sft]; }
        __syncthreads();
    }
    if (t == 0) {
        const float bnf = (float)box_num[b];
        gl_out[b] = r1[0] / (bnf * bnf) + 1e-4f * sqrtf(r2[0]);
    }
}

// ---------------------------------------------------------------------------
// Kernel A: AH0 only (round-13 proven version). c0 fp16, MLP=8.
// ---------------------------------------------------------------------------
__global__ __launch_bounds__(256) void ah0_kernel(
    const float* __restrict__ xi0, const __half* __restrict__ c0,
    const float* __restrict__ rel, const float* __restrict__ Wt,
    const float* __restrict__ adj2, float* __restrict__ AH0)
{
    __shared__ __align__(16) float rel_s[1536];
    __shared__ __align__(16) float wt_s[1536];
    __shared__ __align__(16) float adj_s[256];
    __shared__ __align__(16) float ahred[2048];
    __shared__ __align__(16) float xi_s[256];

    const int t = threadIdx.x;
    const int wid = t >> 5;
    const int lane = t & 31;
    const int row = blockIdx.x;
    const int b = row >> 8;

    const float* relrow = rel + (size_t)row * 256 * 6;
    for (int f = t; f < 1536; f += 256) { rel_s[f] = relrow[f]; wt_s[f] = Wt[f]; }
    adj_s[t] = adj2[row * 256 + t];
    xi_s[t]  = xi0[row * 256 + t];
    __syncthreads();

    const uint2* c0q = reinterpret_cast<const uint2*>(c0 + b * 65536);

#pragma unroll
    for (int kq2 = 0; kq2 < 2; ++kq2) {
        const int q = lane + 32 * kq2;
        const ulonglong2 xiv = *reinterpret_cast<const ulonglong2*>(&xi_s[4 * q]);
        ull_t wt2[6][2];
#pragma unroll
        for (int c = 0; c < 6; ++c) {
            const ulonglong2 w = *reinterpret_cast<const ulonglong2*>(&wt_s[c * 256 + 4 * q]);
            wt2[c][0] = w.x; wt2[c][1] = w.y;
        }

        float ah0 = 0.f, ah1 = 0.f, ah2 = 0.f, ah3 = 0.f;
#pragma unroll 1
        for (int s = 0; s < 32; s += 8) {
            uint2 cv[8];
#pragma unroll
            for (int u = 0; u < 8; ++u)
                cv[u] = __ldg(&c0q[(wid * 32 + s + u) * 64 + q]);
#pragma unroll
            for (int u = 0; u < 8; ++u) {
                const int j = wid * 32 + s + u;
                const float* rj = rel_s + j * 6;
                ull_t t0 = add2(xiv.x, h2_to_pk(cv[u].x));
                ull_t t1 = add2(xiv.y, h2_to_pk(cv[u].y));
#pragma unroll
                for (int c = 0; c < 6; ++c) {
                    const ull_t rp = pk2(rj[c], rj[c]);
                    t0 = fma2(rp, wt2[c][0], t0);
                    t1 = fma2(rp, wt2[c][1], t1);
                }
                float h0, h1, h2, h3;
                upk2(t0, h0, h1);
                upk2(t1, h2, h3);
                const float aw = adj_s[j];
                ah0 = fmaf(aw, fmaxf(h0, 0.f), ah0);
                ah1 = fmaf(aw, fmaxf(h1, 0.f), ah1);
                ah2 = fmaf(aw, fmaxf(h2, 0.f), ah2);
                ah3 = fmaf(aw, fmaxf(h3, 0.f), ah3);
            }
        }
        float4 o; o.x = ah0; o.y = ah1; o.z = ah2; o.w = ah3;
        *reinterpret_cast<float4*>(&ahred[wid * 256 + 4 * q]) = o;
    }
    __syncthreads();

    float s = 0.f;
#pragma unroll
    for (int g = 0; g < 8; ++g) s += ahred[g * 256 + t];
    AH0[row * 256 + t] = s;
}

// ---------------------------------------------------------------------------
// Kernel C: fused layer0 GEMM + layer1 reduction (round-13 proven version).
// ---------------------------------------------------------------------------
// SMEM byte offsets
#define SM_A       0         // 128 j x 256 k fp16, 512B rows, xor-swizzled = 65536
#define SM_B1      65536     // 32768
#define SM_REL     98304     // 3072
#define SM_ADJ     101376    // 1024
#define SM_AHRED   102400    // 8192 (8 warps x 256 n)
#define SM_XI      110592    // 1024
#define SM_XI1     111616    // 1024
#define SM_TOTAL   112640

__global__ void __launch_bounds__(256, 2) layer01_mma_kernel(
    const float* __restrict__ xi0, const __half* __restrict__ c0,
    const float* __restrict__ rel, const float* __restrict__ Wt,
    const float* __restrict__ adj2,
    const float* __restrict__ xi1, const __half* __restrict__ c1,
    float* __restrict__ AH1a, float* __restrict__ AH1b)
{
    extern __shared__ char sm[];
    const uint32_t sb = smem_to_u32(sm);
    float* rel_s  = reinterpret_cast<float*>(sm + SM_REL);
    float* adj_s  = reinterpret_cast<float*>(sm + SM_ADJ);
    float* ah1red = reinterpret_cast<float*>(sm + SM_AHRED);
    float* xi_s   = reinterpret_cast<float*>(sm + SM_XI);
    float* xi1_s  = reinterpret_cast<float*>(sm + SM_XI1);

    const int t = threadIdx.x;
    const int wid = t >> 5;
    const int lane = t & 31;
    const int row = blockIdx.x;      // b*256 + i
    const int jh  = blockIdx.y;      // 0 or 1
    const int b = row >> 8;

    adj_s[t]  = adj2[row * 256 + t];
    xi_s[t]   = xi0[row * 256 + t];
    xi1_s[t]  = xi1[row * 256 + t];
    const float* relrow = rel + ((size_t)row * 256 + jh * 128) * 6;
    for (int f = t; f < 768; f += 256) rel_s[f] = relrow[f];
    __syncthreads();

    const uint2* c0q = reinterpret_cast<const uint2*>(c0 + b * 65536);
    const __half* c1b = c1 + b * 65536;

    // --- per-lane ldmatrix address components ---
    const int jrl = wid * 16 + (lane & 15);
    const uint32_t acolByte = (uint32_t)((lane >> 4) * 16);
    const uint32_t jmask = (uint32_t)((jrl & 7) << 4);
    const uint32_t aRowByte = (uint32_t)jrl * 512u;
    const int nrow_l = (lane & 7) | ((lane & 16) >> 1);
    const uint32_t kbB = (uint32_t)(((lane >> 3) & 1) * 16);
    const uint32_t nmask = (uint32_t)((nrow_l & 7) << 4);
    const uint32_t bRowByte = (uint32_t)nrow_l * 256u;

    const int r  = lane >> 2;    // 0..7
    const int cq = lane & 3;     // 0..3

    // ---- build H half (128 j x 256 k) as fp16; 4 k per iter, MLP=4 ----
#pragma unroll
    for (int kq2 = 0; kq2 < 2; ++kq2) {
        const int q = lane + 32 * kq2;     // k-quad 0..63
        const ulonglong2 xiv = *reinterpret_cast<const ulonglong2*>(&xi_s[4 * q]);
        ull_t wt2[6][2];
#pragma unroll
        for (int c = 0; c < 6; ++c) {
            const float2 wa = __ldg(reinterpret_cast<const float2*>(&Wt[c * 256 + 4 * q]));
            const float2 wb = __ldg(reinterpret_cast<const float2*>(&Wt[c * 256 + 4 * q + 2]));
            wt2[c][0] = pk2(wa.x, wa.y);
            wt2[c][1] = pk2(wb.x, wb.y);
        }

#pragma unroll 1
        for (int s = 0; s < 16; s += 4) {
            uint2 cv[4];
#pragma unroll
            for (int u = 0; u < 4; ++u) {
                const int j = jh * 128 + wid * 16 + s + u;
                cv[u] = __ldg(&c0q[j * 64 + q]);
            }
#pragma unroll
            for (int u = 0; u < 4; ++u) {
                const int jl = wid * 16 + s + u;
                const float* rj = rel_s + jl * 6;
                ull_t t0 = add2(xiv.x, h2_to_pk(cv[u].x));
                ull_t t1 = add2(xiv.y, h2_to_pk(cv[u].y));
#pragma unroll
                for (int c = 0; c < 6; ++c) {
                    const ull_t rp = pk2(rj[c], rj[c]);
                    t0 = fma2(rp, wt2[c][0], t0);
                    t1 = fma2(rp, wt2[c][1], t1);
                }
                float h0, h1, h2, h3;
                upk2(t0, h0, h1);
                upk2(t1, h2, h3);
                __half2 ha = __floats2half2_rn(fmaxf(h0, 0.f), fmaxf(h1, 0.f));
                __half2 hb = __floats2half2_rn(fmaxf(h2, 0.f), fmaxf(h3, 0.f));
                uint2 hv;
                hv.x = *reinterpret_cast<uint32_t*>(&ha);
                hv.y = *reinterpret_cast<uint32_t*>(&hb);
                const uint32_t off = (uint32_t)jl * 512u + ((uint32_t)(8 * q) ^ ((uint32_t)(jl & 7) << 4));
                *reinterpret_cast<uint2*>(sm + SM_A + off) = hv;
            }
        }
    }

#pragma unroll 1
    for (int nc = 0; nc < 2; ++nc) {
        float C[16][4];
#pragma unroll
        for (int nt = 0; nt < 16; ++nt)
#pragma unroll
            for (int u = 0; u < 4; ++u) C[nt][u] = 0.f;

#pragma unroll 1
        for (int kh = 0; kh < 2; ++kh) {
            __syncthreads();   // prior B consumers done (first iter: A build visibility)
            {
                const uint4* s1 = reinterpret_cast<const uint4*>(
                    reinterpret_cast<const char*>(g_wimg1) + kh * 65536 + nc * 32768);
                uint4* d1 = reinterpret_cast<uint4*>(sm + SM_B1);
                for (int i = t; i < 2048; i += 256) d1[i] = __ldg(&s1[i]);
            }
            __syncthreads();

            // ---- HMMA: C += A * B ----
#pragma unroll 1
            for (int ks = 0; ks < 8; ++ks) {
                const uint32_t aoff = ((uint32_t)((kh * 8 + ks) * 32) + acolByte) ^ jmask;
                const uint32_t boff = ((uint32_t)(ks * 32) + kbB) ^ nmask;
                uint32_t Ah[4];
                ldsm4(Ah, sb + SM_A + aRowByte + aoff);

                uint32_t bb[4];
#pragma unroll
                for (int p = 0; p < 8; ++p) {
                    ldsm4(bb, sb + SM_B1 + (uint32_t)p * 4096 + bRowByte + boff);
                    mma_f16(C[2 * p],     Ah, bb[0], bb[1]);
                    mma_f16(C[2 * p + 1], Ah, bb[2], bb[3]);
                }
            }
        }

        // ---- fused layer1 epilogue: consume alpha1 = relu(C) in registers ----
        {
            float acc0[16], acc1[16];
#pragma unroll
            for (int nt = 0; nt < 16; ++nt) { acc0[nt] = 0.f; acc1[nt] = 0.f; }

            const int j1 = jh * 128 + wid * 16 + r;
            const int j2 = j1 + 8;
            const float aw1 = adj_s[j1];
            const float aw2 = adj_s[j2];

#pragma unroll
            for (int ntb = 0; ntb < 16; ntb += 4) {
                uint32_t cA[4], cB[4];
#pragma unroll
                for (int u = 0; u < 4; ++u) {
                    const int n0 = nc * 128 + (ntb + u) * 8 + 2 * cq;
                    cA[u] = __ldg(reinterpret_cast<const uint32_t*>(c1b + j1 * 256 + n0));
                    cB[u] = __ldg(reinterpret_cast<const uint32_t*>(c1b + j2 * 256 + n0));
                }
#pragma unroll
                for (int u = 0; u < 4; ++u) {
                    const int nt = ntb + u;
                    const int n0 = nc * 128 + nt * 8 + 2 * cq;
                    const float2 fA = __half22float2(*reinterpret_cast<const __half2*>(&cA[u]));
                    const float2 fB = __half22float2(*reinterpret_cast<const __half2*>(&cB[u]));
                    const float x0 = xi1_s[n0];
                    const float x1v = xi1_s[n0 + 1];
                    const float a0 = fmaxf(C[nt][0], 0.f);
                    const float a1 = fmaxf(C[nt][1], 0.f);
                    const float a2 = fmaxf(C[nt][2], 0.f);
                    const float a3 = fmaxf(C[nt][3], 0.f);
                    acc0[nt] = fmaf(aw1, fmaxf(x0 + fA.x + a0, 0.f), acc0[nt]);
                    acc1[nt] = fmaf(aw1, fmaxf(x1v + fA.y + a1, 0.f), acc1[nt]);
                    acc0[nt] = fmaf(aw2, fmaxf(x0 + fB.x + a2, 0.f), acc0[nt]);
                    acc1[nt] = fmaf(aw2, fmaxf(x1v + fB.y + a3, 0.f), acc1[nt]);
                }
            }

#pragma unroll
            for (int nt = 0; nt < 16; ++nt) {
                float v0 = acc0[nt], v1 = acc1[nt];
#pragma unroll
                for (int off = 4; off <= 16; off <<= 1) {
                    v0 += __shfl_xor_sync(0xffffffffu, v0, off);
                    v1 += __shfl_xor_sync(0xffffffffu, v1, off);
                }
                if (r == 0) {
                    const int n0 = nc * 128 + nt * 8 + 2 * cq;
                    ah1red[wid * 256 + n0]     = v0;
                    ah1red[wid * 256 + n0 + 1] = v1;
                }
            }
        }
    }
    __syncthreads();

    // cross-warp reduce -> AH1part[jh]
    {
        float s = 0.f;
#pragma unroll
        for (int g = 0; g < 8; ++g) s += ah1red[g * 256 + t];
        float* dst = jh ? AH1b : AH1a;
        dst[row * 256 + t] = s;
    }
}

// ---------------------------------------------------------------------------
extern "C" void kernel_launch(void* const* d_in, const int* in_sizes, int n_in,
                              void* d_out, int out_size)
{
    (void)in_sizes; (void)n_in; (void)out_size;

    const float* x        = (const float*)d_in[0];
    const float* rel      = (const float*)d_in[1];
    const float* adj      = (const float*)d_in[2];
    const int*   bnum     = (const int*)  d_in[3];
    const float* Wt       = (const float*)d_in[4];
    const float* b_alpha  = (const float*)d_in[5];
    const float* W_proj   = (const float*)d_in[6];
    const float* b_proj   = (const float*)d_in[7];
    const float* learn_w  = (const float*)d_in[8];
    const float* w_alpha0 = (const float*)d_in[9];
    const float* w_vi0    = (const float*)d_in[10];
    const float* w_vj0    = (const float*)d_in[11];
    const float* bias_h0  = (const float*)d_in[12];
    const float* w_node0  = (const float*)d_in[13];
    /* d_in[14] = l1_w_alpha: unused (alpha2 discarded) */
    const float* w_vi1    = (const float*)d_in[15];
    const float* w_vj1    = (const float*)d_in[16];
    const float* bias_h1  = (const float*)d_in[17];
    const float* w_node1  = (const float*)d_in[18];

    float* out      = (float*)d_out;
    float* out_x2   = out;
    float* out_sadj = out + 262144;
    float* out_gl   = out + 524288;

    float *xhat, *pnorm, *adj2, *xi0, *AH0, *xi1, *AH1a, *AH1b;
    __half *c0, *c1;
    cudaGetSymbolAddress((void**)&xhat,  g_xhat);
    cudaGetSymbolAddress((void**)&pnorm, g_pnorm);
    cudaGetSymbolAddress((void**)&adj2,  g_adj2);
    cudaGetSymbolAddress((void**)&xi0,   g_xi0);
    cudaGetSymbolAddress((void**)&c0,    g_c0);
    cudaGetSymbolAddress((void**)&AH0,   g_AH0);
    cudaGetSymbolAddress((void**)&xi1,   g_xi1);
    cudaGetSymbolAddress((void**)&c1,    g_c1);
    cudaGetSymbolAddress((void**)&AH1a,  g_AH1a);
    cudaGetSymbolAddress((void**)&AH1b,  g_AH1b);

    const int PIPE2_SMEM = (2048 + 2 * 8192) * 4;   // 73728 B (single-W pipelined)
    const int PIPE4_SMEM = (2048 + 4 * 8192) * 4;   // 139264 B (dual-W pipelined)

    cudaFuncSetAttribute(rowgemm8_dual_prep_kernel, cudaFuncAttributeMaxDynamicSharedMemorySize, PIPE4_SMEM);
    rowgemm8_dual_prep_kernel<<<128, 256, PIPE4_SMEM>>>(x, w_vi0, w_vj0, bias_h0, b_alpha, w_alpha0, xi0, c0);

    rowgemm_kernel<<<256, 128>>>(x, W_proj, b_proj, xhat);
    pair_softadj_kernel<<<1024, 256>>>(xhat, adj, learn_w, bnum, out_sadj, adj2, pnorm);

    ah0_kernel<<<1024, 256>>>(xi0, c0, rel, Wt, adj2, AH0);
    cudaFuncSetAttribute(chain_kernel, cudaFuncAttributeMaxDynamicSharedMemorySize, PIPE4_SMEM);
    chain_kernel<<<128, 256, PIPE4_SMEM>>>(AH0, w_node0, w_vi1, w_vj1, bias_h1, xi1, c1);

    cudaFuncSetAttribute(layer01_mma_kernel, cudaFuncAttributeMaxDynamicSharedMemorySize, SM_TOTAL);
    layer01_mma_kernel<<<dim3(1024, 2), 256, SM_TOTAL>>>(xi0, c0, rel, Wt, adj2, xi1, c1, AH1a, AH1b);

    glloss_part_kernel<<<512, 256>>>(out_sadj, pnorm);
    glloss_fin_kernel<<<4, 128>>>(bnum, out_gl);

    cudaFuncSetAttribute(rowgemm8_sum_kernel, cudaFuncAttributeMaxDynamicSharedMemorySize, PIPE2_SMEM);
    rowgemm8_sum_kernel<<<128, 256, PIPE2_SMEM>>>(AH1a, AH1b, w_node1, out_x2);
}